// round 3
// baseline (speedup 1.0000x reference)
#include <cuda_runtime.h>
#include <cstdint>
#include <cstddef>

// Problem constants
#define S_LEN   2048
#define HDIM    2048
#define NHEADS  16
#define HD      128
#define BATCH   2
#define QKV_N   6144           // 3*HDIM
#define SCALE   0.08838834764831845f   // 1/sqrt(128)
#define QK_PAD  68             // transposed-tile stride; MUST be multiple of 4 for float4 LDS

// Scratch (device globals — allocation-free per harness rules)
__device__ float g_qkv[(size_t)BATCH * S_LEN * QKV_N];   // [B, S, 3H] natural layout
__device__ float g_att[(size_t)BATCH * S_LEN * HDIM];    // attention output, [B, S, H]

// ---------------------------------------------------------------------------
// SGEMM: C[M,N] = A[M,K] @ B[K,N] + bias[N]
// 128x128 block, 16 K-slice, 8x8 per-thread microtile, 256 threads.
// ---------------------------------------------------------------------------
__global__ __launch_bounds__(256, 2)
void sgemm_bias_kernel(const float* __restrict__ A, const float* __restrict__ B,
                       const float* __restrict__ bias, float* __restrict__ C,
                       int M, int N, int K)
{
    __shared__ float As[16][128];   // transposed: As[k][m]
    __shared__ float Bs[16][128];   // Bs[k][n]

    const int tid = threadIdx.x;
    const int tx  = tid & 15;       // 0..15  (N direction)
    const int ty  = tid >> 4;       // 0..15  (M direction)
    const int bm  = blockIdx.y << 7;
    const int bn  = blockIdx.x << 7;

    float acc[8][8];
#pragma unroll
    for (int i = 0; i < 8; i++)
#pragma unroll
        for (int j = 0; j < 8; j++) acc[i][j] = 0.0f;

    const int ar = tid >> 2;          // 0..63
    const int ac = (tid & 3) << 2;    // 0,4,8,12
    const int br = tid >> 5;          // 0..7
    const int bc = (tid & 31) << 2;   // 0..124

    for (int k0 = 0; k0 < K; k0 += 16) {
        // Load A tile (128 x 16) transposed into As
#pragma unroll
        for (int i = 0; i < 2; i++) {
            int row = ar + (i << 6);
            float4 a = *(const float4*)(A + (size_t)(bm + row) * K + k0 + ac);
            As[ac + 0][row] = a.x;
            As[ac + 1][row] = a.y;
            As[ac + 2][row] = a.z;
            As[ac + 3][row] = a.w;
        }
        // Load B tile (16 x 128)
#pragma unroll
        for (int i = 0; i < 2; i++) {
            int row = br + (i << 3);
            *(float4*)&Bs[row][bc] =
                *(const float4*)(B + (size_t)(k0 + row) * N + bn + bc);
        }
        __syncthreads();

#pragma unroll
        for (int kk = 0; kk < 16; kk++) {
            float4 a0 = *(float4*)&As[kk][ty * 8];
            float4 a1 = *(float4*)&As[kk][ty * 8 + 4];
            float4 b0 = *(float4*)&Bs[kk][tx * 8];
            float4 b1 = *(float4*)&Bs[kk][tx * 8 + 4];
            float av[8] = {a0.x, a0.y, a0.z, a0.w, a1.x, a1.y, a1.z, a1.w};
            float bv[8] = {b0.x, b0.y, b0.z, b0.w, b1.x, b1.y, b1.z, b1.w};
#pragma unroll
            for (int i = 0; i < 8; i++)
#pragma unroll
                for (int j = 0; j < 8; j++)
                    acc[i][j] = fmaf(av[i], bv[j], acc[i][j]);
        }
        __syncthreads();
    }

    // Epilogue: add bias, write
    float bvreg[8];
#pragma unroll
    for (int j = 0; j < 8; j++) bvreg[j] = bias[bn + tx * 8 + j];

#pragma unroll
    for (int i = 0; i < 8; i++) {
        float* crow = C + (size_t)(bm + ty * 8 + i) * N + bn + tx * 8;
        float4 o0, o1;
        o0.x = acc[i][0] + bvreg[0];
        o0.y = acc[i][1] + bvreg[1];
        o0.z = acc[i][2] + bvreg[2];
        o0.w = acc[i][3] + bvreg[3];
        o1.x = acc[i][4] + bvreg[4];
        o1.y = acc[i][5] + bvreg[5];
        o1.z = acc[i][6] + bvreg[6];
        o1.w = acc[i][7] + bvreg[7];
        *(float4*)(crow)     = o0;
        *(float4*)(crow + 4) = o1;
    }
}

// ---------------------------------------------------------------------------
// Flash attention over the "plain reshape" head split:
//   Qh[q][d] = qkv[b][nh*128 + q/16][(q%16)*128 + d + 0]
//   Kh[k][d] = ... + 2048,  Vh[k][d] = ... + 4096
// Causal mask on (q,k) in reshaped coordinates. Output written in [B,S,H]
// natural layout: att[b][q][nh*128 + d].
// One CTA per (q-tile of 64, head, batch). 256 threads = 16x16.
// ---------------------------------------------------------------------------
__global__ __launch_bounds__(256, 1)
void attn_kernel(float* __restrict__ att_out)
{
    const int qt  = blockIdx.x;     // 0..31
    const int nh  = blockIdx.y;     // 0..15
    const int b   = blockIdx.z;     // 0..1
    const int tid = threadIdx.x;
    const int tx  = tid & 15;       // key/col direction
    const int ty  = tid >> 4;       // query/row direction
    const int q0  = qt * 64;

    extern __shared__ float sm[];
    float* Qs = sm;                       // [128][QK_PAD] transposed, 16B-aligned rows
    float* Ks = Qs + 128 * QK_PAD;        // [128][QK_PAD] transposed
    float* Vs = Ks + 128 * QK_PAD;        // [64][128]  row-major
    float* Ss = Vs + 64 * 128;            // [64][65]   P tile (scalar access only)

    const size_t base_bh = ((size_t)b * S_LEN + (size_t)nh * HD) * QKV_N;

    // Load Q tile (64 rows x 128 d), transposed into Qs
    for (int idx = tid; idx < 64 * 32; idx += 256) {
        int r  = idx >> 5;
        int d4 = (idx & 31) << 2;
        int qg = q0 + r;
        const float* p = g_qkv + base_bh + (size_t)(qg >> 4) * QKV_N + ((qg & 15) << 7);
        float4 v = *(const float4*)(p + d4);
        Qs[(d4 + 0) * QK_PAD + r] = v.x;
        Qs[(d4 + 1) * QK_PAD + r] = v.y;
        Qs[(d4 + 2) * QK_PAD + r] = v.z;
        Qs[(d4 + 3) * QK_PAD + r] = v.w;
    }

    float O[4][8];
#pragma unroll
    for (int i = 0; i < 4; i++)
#pragma unroll
        for (int j = 0; j < 8; j++) O[i][j] = 0.0f;

    float m_run[4], l_run[4];
#pragma unroll
    for (int i = 0; i < 4; i++) { m_run[i] = -1e30f; l_run[i] = 0.0f; }

    for (int kt = 0; kt <= qt; kt++) {
        __syncthreads();   // protect Ks/Vs/Ss reuse from previous iteration
        const int k0 = kt * 64;

        // Load K tile (transposed) and V tile (row-major)
        for (int idx = tid; idx < 64 * 32; idx += 256) {
            int r  = idx >> 5;
            int d4 = (idx & 31) << 2;
            int kg = k0 + r;
            const float* p = g_qkv + base_bh + (size_t)(kg >> 4) * QKV_N + ((kg & 15) << 7);
            float4 kv = *(const float4*)(p + d4 + HDIM);
            Ks[(d4 + 0) * QK_PAD + r] = kv.x;
            Ks[(d4 + 1) * QK_PAD + r] = kv.y;
            Ks[(d4 + 2) * QK_PAD + r] = kv.z;
            Ks[(d4 + 3) * QK_PAD + r] = kv.w;
            float4 vv = *(const float4*)(p + d4 + 2 * HDIM);
            *(float4*)&Vs[r * 128 + d4] = vv;
        }
        __syncthreads();

        // Scores: S[64][64] = Q @ K^T ; each thread 4x4 microtile
        float sc[4][4];
#pragma unroll
        for (int i = 0; i < 4; i++)
#pragma unroll
            for (int j = 0; j < 4; j++) sc[i][j] = 0.0f;

#pragma unroll 8
        for (int d = 0; d < 128; d++) {
            float4 qa = *(float4*)&Qs[d * QK_PAD + ty * 4];
            float4 kb = *(float4*)&Ks[d * QK_PAD + tx * 4];
            float qv[4] = {qa.x, qa.y, qa.z, qa.w};
            float kv[4] = {kb.x, kb.y, kb.z, kb.w};
#pragma unroll
            for (int i = 0; i < 4; i++)
#pragma unroll
                for (int j = 0; j < 4; j++)
                    sc[i][j] = fmaf(qv[i], kv[j], sc[i][j]);
        }

        const bool diag = (kt == qt);
#pragma unroll
        for (int i = 0; i < 4; i++) {
            const int qg = q0 + ty * 4 + i;
            float rm = -1e30f;
#pragma unroll
            for (int j = 0; j < 4; j++) {
                float v = sc[i][j] * SCALE;
                if (diag && (k0 + tx * 4 + j) > qg) v = -1e30f;
                sc[i][j] = v;
                rm = fmaxf(rm, v);
            }
            // row-max across the 16 tx lanes (xor widths < 16 stay in-group)
#pragma unroll
            for (int o = 8; o > 0; o >>= 1)
                rm = fmaxf(rm, __shfl_xor_sync(0xffffffffu, rm, o));

            float mn   = fmaxf(m_run[i], rm);
            float corr = __expf(m_run[i] - mn);
            m_run[i]   = mn;

            float rs = 0.0f;
#pragma unroll
            for (int j = 0; j < 4; j++) {
                float pj = __expf(sc[i][j] - mn);
                Ss[(ty * 4 + i) * 65 + tx * 4 + j] = pj;
                rs += pj;
            }
#pragma unroll
            for (int o = 8; o > 0; o >>= 1)
                rs += __shfl_xor_sync(0xffffffffu, rs, o);

            l_run[i] = l_run[i] * corr + rs;
#pragma unroll
            for (int j = 0; j < 8; j++) O[i][j] *= corr;
        }
        __syncthreads();

        // O += P @ V   (P from Ss, V from Vs)
#pragma unroll 2
        for (int k = 0; k < 64; k++) {
            float4 v0 = *(float4*)&Vs[k * 128 + tx * 8];
            float4 v1 = *(float4*)&Vs[k * 128 + tx * 8 + 4];
#pragma unroll
            for (int i = 0; i < 4; i++) {
                float p = Ss[(ty * 4 + i) * 65 + k];
                O[i][0] = fmaf(p, v0.x, O[i][0]);
                O[i][1] = fmaf(p, v0.y, O[i][1]);
                O[i][2] = fmaf(p, v0.z, O[i][2]);
                O[i][3] = fmaf(p, v0.w, O[i][3]);
                O[i][4] = fmaf(p, v1.x, O[i][4]);
                O[i][5] = fmaf(p, v1.y, O[i][5]);
                O[i][6] = fmaf(p, v1.z, O[i][6]);
                O[i][7] = fmaf(p, v1.w, O[i][7]);
            }
        }
    }

    // Epilogue: normalize and store to [B,S,H] natural layout
#pragma unroll
    for (int i = 0; i < 4; i++) {
        const int qg  = q0 + ty * 4 + i;
        const float inv = 1.0f / l_run[i];
        float* op = att_out + ((size_t)b * S_LEN + qg) * HDIM + nh * HD + tx * 8;
        float4 o0, o1;
        o0.x = O[i][0] * inv; o0.y = O[i][1] * inv;
        o0.z = O[i][2] * inv; o0.w = O[i][3] * inv;
        o1.x = O[i][4] * inv; o1.y = O[i][5] * inv;
        o1.z = O[i][6] * inv; o1.w = O[i][7] * inv;
        *(float4*)(op)     = o0;
        *(float4*)(op + 4) = o1;
    }
}

// ---------------------------------------------------------------------------
// Launch
// inputs (metadata order): hidden_states [2,2048,2048] f32, attention_mask
// [1,1,2048,2048] f32 (causal, re-derived analytically), W_attn [2048,6144],
// b_attn [6144], W_proj [2048,2048], b_proj [2048]. Output [2,2048,2048] f32.
// ---------------------------------------------------------------------------
extern "C" void kernel_launch(void* const* d_in, const int* in_sizes, int n_in,
                              void* d_out, int out_size)
{
    const float* hidden = (const float*)d_in[0];
    // d_in[1] = attention_mask (causal -1e9; handled analytically in-kernel)
    const float* W_attn = (const float*)d_in[2];
    const float* b_attn = (const float*)d_in[3];
    const float* W_proj = (const float*)d_in[4];
    const float* b_proj = (const float*)d_in[5];
    float* out = (float*)d_out;

    float* qkv = nullptr;
    float* att = nullptr;
    cudaGetSymbolAddress((void**)&qkv, g_qkv);
    cudaGetSymbolAddress((void**)&att, g_att);

    const int M = BATCH * S_LEN;   // 4096

    // 1) QKV projection: [4096,2048] @ [2048,6144] + b
    {
        dim3 grid(QKV_N / 128, M / 128);
        sgemm_bias_kernel<<<grid, 256>>>(hidden, W_attn, b_attn, qkv,
                                         M, QKV_N, HDIM);
    }

    // 2) Attention (scrambled reshape-split heads, causal, flash-style)
    {
        static const size_t smem_bytes =
            (size_t)(128 * QK_PAD * 2 + 64 * 128 + 64 * 65) * sizeof(float); // 119296 B
        cudaFuncSetAttribute(attn_kernel,
                             cudaFuncAttributeMaxDynamicSharedMemorySize,
                             (int)smem_bytes);
        dim3 grid(S_LEN / 64, NHEADS, BATCH);
        attn_kernel<<<grid, 256, smem_bytes>>>(att);
    }

    // 3) Output projection: [4096,2048] @ [2048,2048] + b -> d_out
    {
        dim3 grid(HDIM / 128, M / 128);
        sgemm_bias_kernel<<<grid, 256>>>(att, W_proj, b_proj, out,
                                         M, HDIM, HDIM);
    }
}

// round 5
// speedup vs baseline: 1.5298x; 1.5298x over previous
#include <cuda_runtime.h>
#include <cstdint>
#include <cstddef>

// Problem constants
#define S_LEN   2048
#define HDIM    2048
#define NHEADS  16
#define HD      128
#define BATCH   2
#define QKV_N   6144
#define SCALE   0.08838834764831845f
#define QK_PAD  68
#define TPAD    40      // gemm smem tile row stride (floats); mult of 4 for float4

// Scratch (device globals — allocation-free per harness rules)
__device__ float g_qkv[(size_t)BATCH * S_LEN * QKV_N];    // [B, S, 3H]
__device__ float g_att[(size_t)BATCH * S_LEN * HDIM];     // attention out [B, S, H]
__device__ float g_wta[(size_t)QKV_N * HDIM];             // W_attn^T  [6144, 2048]
__device__ float g_wtp[(size_t)HDIM * HDIM];              // W_proj^T  [2048, 2048]

__device__ __forceinline__ uint32_t f2tf32(float x) {
    uint32_t r;
    asm("cvt.rna.tf32.f32 %0, %1;" : "=r"(r) : "f"(x));
    return r;
}

// m16n8k8 tf32 MMA, fp32 accumulate (sm_80+ legacy tensor path — works on sm_100)
__device__ __forceinline__ void mma_tf32(float* c, const uint32_t* a, const uint32_t* b) {
    asm volatile(
        "mma.sync.aligned.m16n8k8.row.col.f32.tf32.tf32.f32 "
        "{%0,%1,%2,%3}, {%4,%5,%6,%7}, {%8,%9}, {%0,%1,%2,%3};"
        : "+f"(c[0]), "+f"(c[1]), "+f"(c[2]), "+f"(c[3])
        : "r"(a[0]), "r"(a[1]), "r"(a[2]), "r"(a[3]), "r"(b[0]), "r"(b[1]));
}

// ---------------------------------------------------------------------------
// Transpose: out[C][R] = in[R][C]   (weights -> K-major for coalesced B fill)
// ---------------------------------------------------------------------------
__global__ void transpose_kernel(const float* __restrict__ in, float* __restrict__ out,
                                 int R, int C)
{
    __shared__ float t[32][33];
    const int bx = blockIdx.x * 32;
    const int by = blockIdx.y * 32;
#pragma unroll
    for (int i = 0; i < 32; i += 8)
        t[threadIdx.y + i][threadIdx.x] = in[(size_t)(by + threadIdx.y + i) * C + bx + threadIdx.x];
    __syncthreads();
#pragma unroll
    for (int i = 0; i < 32; i += 8)
        out[(size_t)(bx + threadIdx.y + i) * R + by + threadIdx.x] = t[threadIdx.x][threadIdx.y + i];
}

// ---------------------------------------------------------------------------
// tf32 mma.sync GEMM: C[M,N] = A[M,K] @ Bt[N,K]^T + bias[N]
// CTA 128x128, 256 threads (8 warps = 2m x 4n), warp tile 64x32 (4x4 m16n8k8),
// K-chunk 32, double-buffered padded smem tiles, reg-prefetch pipeline.
// ---------------------------------------------------------------------------
#define STAGE_FLOATS (2 * 128 * TPAD)              // A tile + B tile, one stage
#define GEMM_SMEM    (2 * STAGE_FLOATS * 4)        // 81920 bytes

__global__ __launch_bounds__(256)
void gemm_tf32_kernel(const float* __restrict__ A, const float* __restrict__ Bt,
                      const float* __restrict__ bias, float* __restrict__ C,
                      int M, int N, int K)
{
    extern __shared__ float sm[];
    const int tid    = threadIdx.x;
    const int lane   = tid & 31;
    const int wid    = tid >> 5;
    const int g      = lane >> 2;       // groupID 0..7
    const int t      = lane & 3;        // threadID_in_group 0..3
    const int warp_m = wid & 1;         // 0..1 (64 rows each)
    const int warp_n = wid >> 1;        // 0..3 (32 cols each)
    const int m0     = blockIdx.y << 7;
    const int n0     = blockIdx.x << 7;

    const float* Ap = A  + (size_t)m0 * K;
    const float* Bp = Bt + (size_t)n0 * K;

    float acc[4][4][4];
#pragma unroll
    for (int mt = 0; mt < 4; mt++)
#pragma unroll
        for (int nt = 0; nt < 4; nt++)
#pragma unroll
            for (int k = 0; k < 4; k++) acc[mt][nt][k] = 0.0f;

    // bias fragment (cols 2t, 2t+1 of each n-tile)
    float2 bv[4];
#pragma unroll
    for (int nt = 0; nt < 4; nt++)
        bv[nt] = *(const float2*)(bias + n0 + warp_n * 32 + nt * 8 + 2 * t);

    const int nchunks = K >> 5;

    // --- prefill chunk 0 into stage 0 ---
#pragma unroll
    for (int i = 0; i < 4; i++) {
        const int slot = tid + (i << 8);
        const int r    = slot >> 3;
        const int c4   = (slot & 7) << 2;
        float4 va = *(const float4*)(Ap + (size_t)r * K + c4);
        float4 vb = *(const float4*)(Bp + (size_t)r * K + c4);
        uint4 wa, wb;
        wa.x = f2tf32(va.x); wa.y = f2tf32(va.y); wa.z = f2tf32(va.z); wa.w = f2tf32(va.w);
        wb.x = f2tf32(vb.x); wb.y = f2tf32(vb.y); wb.z = f2tf32(vb.z); wb.w = f2tf32(vb.w);
        *(uint4*)(sm + r * TPAD + c4)              = wa;
        *(uint4*)(sm + 128 * TPAD + r * TPAD + c4) = wb;
    }
    __syncthreads();

    for (int c = 0; c < nchunks; ++c) {
        const int s = c & 1;
        const bool has_next = (c + 1) < nchunks;

        // prefetch next chunk (global -> regs)
        float4 pa[4], pb[4];
        if (has_next) {
            const int kcn = (c + 1) << 5;
#pragma unroll
            for (int i = 0; i < 4; i++) {
                const int slot = tid + (i << 8);
                const int r    = slot >> 3;
                const int c4   = (slot & 7) << 2;
                pa[i] = *(const float4*)(Ap + (size_t)r * K + kcn + c4);
                pb[i] = *(const float4*)(Bp + (size_t)r * K + kcn + c4);
            }
        }

        // compute on stage s
        const float* sA = sm + s * STAGE_FLOATS;
        const float* sB = sA + 128 * TPAD;
#pragma unroll
        for (int ks = 0; ks < 4; ks++) {
            const int kof = ks * 8 + t;
            uint32_t afr[4][4], bfr[4][2];
#pragma unroll
            for (int mt = 0; mt < 4; mt++) {
                const int rb = (warp_m * 64 + mt * 16 + g) * TPAD + kof;
                afr[mt][0] = __float_as_uint(sA[rb]);
                afr[mt][1] = __float_as_uint(sA[rb + 8 * TPAD]);
                afr[mt][2] = __float_as_uint(sA[rb + 4]);
                afr[mt][3] = __float_as_uint(sA[rb + 8 * TPAD + 4]);
            }
#pragma unroll
            for (int nt = 0; nt < 4; nt++) {
                const int nb = (warp_n * 32 + nt * 8 + g) * TPAD + kof;
                bfr[nt][0] = __float_as_uint(sB[nb]);
                bfr[nt][1] = __float_as_uint(sB[nb + 4]);
            }
#pragma unroll
            for (int mt = 0; mt < 4; mt++)
#pragma unroll
                for (int nt = 0; nt < 4; nt++)
                    mma_tf32(acc[mt][nt], afr[mt], bfr[nt]);
        }

        // store prefetched chunk into the other stage
        if (has_next) {
            float* dA = sm + (s ^ 1) * STAGE_FLOATS;
            float* dB = dA + 128 * TPAD;
#pragma unroll
            for (int i = 0; i < 4; i++) {
                const int slot = tid + (i << 8);
                const int r    = slot >> 3;
                const int c4   = (slot & 7) << 2;
                uint4 wa, wb;
                wa.x = f2tf32(pa[i].x); wa.y = f2tf32(pa[i].y);
                wa.z = f2tf32(pa[i].z); wa.w = f2tf32(pa[i].w);
                wb.x = f2tf32(pb[i].x); wb.y = f2tf32(pb[i].y);
                wb.z = f2tf32(pb[i].z); wb.w = f2tf32(pb[i].w);
                *(uint4*)(dA + r * TPAD + c4) = wa;
                *(uint4*)(dB + r * TPAD + c4) = wb;
            }
        }
        __syncthreads();
    }

    // epilogue: bias + store (float2 per row-half)
#pragma unroll
    for (int mt = 0; mt < 4; mt++) {
        const int row0 = m0 + warp_m * 64 + mt * 16 + g;
#pragma unroll
        for (int nt = 0; nt < 4; nt++) {
            const int col = n0 + warp_n * 32 + nt * 8 + 2 * t;
            float2 v0, v1;
            v0.x = acc[mt][nt][0] + bv[nt].x;
            v0.y = acc[mt][nt][1] + bv[nt].y;
            v1.x = acc[mt][nt][2] + bv[nt].x;
            v1.y = acc[mt][nt][3] + bv[nt].y;
            *(float2*)(C + (size_t)row0 * N + col)       = v0;
            *(float2*)(C + (size_t)(row0 + 8) * N + col) = v1;
        }
    }
}

// ---------------------------------------------------------------------------
// Flash attention (fp32) over the "plain reshape" head split — unchanged.
// ---------------------------------------------------------------------------
__global__ __launch_bounds__(256, 1)
void attn_kernel(float* __restrict__ att_out)
{
    const int qt  = blockIdx.x;
    const int nh  = blockIdx.y;
    const int b   = blockIdx.z;
    const int tid = threadIdx.x;
    const int tx  = tid & 15;
    const int ty  = tid >> 4;
    const int q0  = qt * 64;

    extern __shared__ float smf[];
    float* Qs = smf;
    float* Ks = Qs + 128 * QK_PAD;
    float* Vs = Ks + 128 * QK_PAD;
    float* Ss = Vs + 64 * 128;

    const size_t base_bh = ((size_t)b * S_LEN + (size_t)nh * HD) * QKV_N;

    for (int idx = tid; idx < 64 * 32; idx += 256) {
        int r  = idx >> 5;
        int d4 = (idx & 31) << 2;
        int qg = q0 + r;
        const float* p = g_qkv + base_bh + (size_t)(qg >> 4) * QKV_N + ((qg & 15) << 7);
        float4 v = *(const float4*)(p + d4);
        Qs[(d4 + 0) * QK_PAD + r] = v.x;
        Qs[(d4 + 1) * QK_PAD + r] = v.y;
        Qs[(d4 + 2) * QK_PAD + r] = v.z;
        Qs[(d4 + 3) * QK_PAD + r] = v.w;
    }

    float O[4][8];
#pragma unroll
    for (int i = 0; i < 4; i++)
#pragma unroll
        for (int j = 0; j < 8; j++) O[i][j] = 0.0f;

    float m_run[4], l_run[4];
#pragma unroll
    for (int i = 0; i < 4; i++) { m_run[i] = -1e30f; l_run[i] = 0.0f; }

    for (int kt = 0; kt <= qt; kt++) {
        __syncthreads();
        const int k0 = kt * 64;

        for (int idx = tid; idx < 64 * 32; idx += 256) {
            int r  = idx >> 5;
            int d4 = (idx & 31) << 2;
            int kg = k0 + r;
            const float* p = g_qkv + base_bh + (size_t)(kg >> 4) * QKV_N + ((kg & 15) << 7);
            float4 kv = *(const float4*)(p + d4 + HDIM);
            Ks[(d4 + 0) * QK_PAD + r] = kv.x;
            Ks[(d4 + 1) * QK_PAD + r] = kv.y;
            Ks[(d4 + 2) * QK_PAD + r] = kv.z;
            Ks[(d4 + 3) * QK_PAD + r] = kv.w;
            float4 vv = *(const float4*)(p + d4 + 2 * HDIM);
            *(float4*)&Vs[r * 128 + d4] = vv;
        }
        __syncthreads();

        float sc[4][4];
#pragma unroll
        for (int i = 0; i < 4; i++)
#pragma unroll
            for (int j = 0; j < 4; j++) sc[i][j] = 0.0f;

#pragma unroll 8
        for (int d = 0; d < 128; d++) {
            float4 qa = *(float4*)&Qs[d * QK_PAD + ty * 4];
            float4 kb = *(float4*)&Ks[d * QK_PAD + tx * 4];
            float qv[4] = {qa.x, qa.y, qa.z, qa.w};
            float kv[4] = {kb.x, kb.y, kb.z, kb.w};
#pragma unroll
            for (int i = 0; i < 4; i++)
#pragma unroll
                for (int j = 0; j < 4; j++)
                    sc[i][j] = fmaf(qv[i], kv[j], sc[i][j]);
        }

        const bool diag = (kt == qt);
#pragma unroll
        for (int i = 0; i < 4; i++) {
            const int qg = q0 + ty * 4 + i;
            float rm = -1e30f;
#pragma unroll
            for (int j = 0; j < 4; j++) {
                float v = sc[i][j] * SCALE;
                if (diag && (k0 + tx * 4 + j) > qg) v = -1e30f;
                sc[i][j] = v;
                rm = fmaxf(rm, v);
            }
#pragma unroll
            for (int o = 8; o > 0; o >>= 1)
                rm = fmaxf(rm, __shfl_xor_sync(0xffffffffu, rm, o));

            float mn   = fmaxf(m_run[i], rm);
            float corr = __expf(m_run[i] - mn);
            m_run[i]   = mn;

            float rs = 0.0f;
#pragma unroll
            for (int j = 0; j < 4; j++) {
                float pj = __expf(sc[i][j] - mn);
                Ss[(ty * 4 + i) * 65 + tx * 4 + j] = pj;
                rs += pj;
            }
#pragma unroll
            for (int o = 8; o > 0; o >>= 1)
                rs += __shfl_xor_sync(0xffffffffu, rs, o);

            l_run[i] = l_run[i] * corr + rs;
#pragma unroll
            for (int j = 0; j < 8; j++) O[i][j] *= corr;
        }
        __syncthreads();

#pragma unroll 2
        for (int k = 0; k < 64; k++) {
            float4 v0 = *(float4*)&Vs[k * 128 + tx * 8];
            float4 v1 = *(float4*)&Vs[k * 128 + tx * 8 + 4];
#pragma unroll
            for (int i = 0; i < 4; i++) {
                float p = Ss[(ty * 4 + i) * 65 + k];
                O[i][0] = fmaf(p, v0.x, O[i][0]);
                O[i][1] = fmaf(p, v0.y, O[i][1]);
                O[i][2] = fmaf(p, v0.z, O[i][2]);
                O[i][3] = fmaf(p, v0.w, O[i][3]);
                O[i][4] = fmaf(p, v1.x, O[i][4]);
                O[i][5] = fmaf(p, v1.y, O[i][5]);
                O[i][6] = fmaf(p, v1.z, O[i][6]);
                O[i][7] = fmaf(p, v1.w, O[i][7]);
            }
        }
    }

#pragma unroll
    for (int i = 0; i < 4; i++) {
        const int qg  = q0 + ty * 4 + i;
        const float inv = 1.0f / l_run[i];
        float* op = att_out + ((size_t)b * S_LEN + qg) * HDIM + nh * HD + tx * 8;
        float4 o0, o1;
        o0.x = O[i][0] * inv; o0.y = O[i][1] * inv;
        o0.z = O[i][2] * inv; o0.w = O[i][3] * inv;
        o1.x = O[i][4] * inv; o1.y = O[i][5] * inv;
        o1.z = O[i][6] * inv; o1.w = O[i][7] * inv;
        *(float4*)(op)     = o0;
        *(float4*)(op + 4) = o1;
    }
}

// ---------------------------------------------------------------------------
// Launch
// ---------------------------------------------------------------------------
extern "C" void kernel_launch(void* const* d_in, const int* in_sizes, int n_in,
                              void* d_out, int out_size)
{
    const float* hidden = (const float*)d_in[0];
    const float* W_attn = (const float*)d_in[2];
    const float* b_attn = (const float*)d_in[3];
    const float* W_proj = (const float*)d_in[4];
    const float* b_proj = (const float*)d_in[5];
    float* out = (float*)d_out;

    float *qkv, *att, *wta, *wtp;
    cudaGetSymbolAddress((void**)&qkv, g_qkv);
    cudaGetSymbolAddress((void**)&att, g_att);
    cudaGetSymbolAddress((void**)&wta, g_wta);
    cudaGetSymbolAddress((void**)&wtp, g_wtp);

    const int M = BATCH * S_LEN;   // 4096

    // 0) Transpose weights to K-major (coalesced B-tile fills)
    {
        dim3 blk(32, 8);
        transpose_kernel<<<dim3(QKV_N / 32, HDIM / 32), blk>>>(W_attn, wta, HDIM, QKV_N);
        transpose_kernel<<<dim3(HDIM / 32, HDIM / 32), blk>>>(W_proj, wtp, HDIM, HDIM);
    }

    cudaFuncSetAttribute(gemm_tf32_kernel,
                         cudaFuncAttributeMaxDynamicSharedMemorySize, GEMM_SMEM);

    // 1) QKV projection (tf32 mma.sync)
    gemm_tf32_kernel<<<dim3(QKV_N / 128, M / 128), 256, GEMM_SMEM>>>(
        hidden, wta, b_attn, qkv, M, QKV_N, HDIM);

    // 2) Attention
    {
        static const size_t smem_bytes =
            (size_t)(128 * QK_PAD * 2 + 64 * 128 + 64 * 65) * sizeof(float);
        cudaFuncSetAttribute(attn_kernel,
                             cudaFuncAttributeMaxDynamicSharedMemorySize,
                             (int)smem_bytes);
        dim3 grid(S_LEN / 64, NHEADS, BATCH);
        attn_kernel<<<grid, 256, smem_bytes>>>(att);
    }

    // 3) Output projection (tf32 mma.sync)
    gemm_tf32_kernel<<<dim3(HDIM / 128, M / 128), 256, GEMM_SMEM>>>(
        att, wtp, b_proj, out, M, HDIM, HDIM);
}

// round 6
// speedup vs baseline: 2.4596x; 1.6078x over previous
#include <cuda_runtime.h>
#include <cstdint>
#include <cstddef>

// Problem constants
#define S_LEN   2048
#define HDIM    2048
#define NHEADS  16
#define HD      128
#define BATCH   2
#define QKV_N   6144
#define SCALE   0.08838834764831845f
#define TPAD    40      // gemm smem tile row stride

// Attention smem layout (floats): Q[128*132], then K0,V0,K1,V1 each 64*132
#define AT_STR        132
#define ATT_Q_FLOATS  (128 * AT_STR)
#define ATT_KV_FLOATS (64 * AT_STR)
#define ATT_SMEM_B    ((ATT_Q_FLOATS + 4 * ATT_KV_FLOATS) * 4)   // 202752

// Scratch (device globals — allocation-free per harness rules)
__device__ float g_qkv[(size_t)BATCH * S_LEN * QKV_N];    // [B, S, 3H]
__device__ float g_att[(size_t)BATCH * S_LEN * HDIM];     // attention out [B, S, H]
__device__ float g_wta[(size_t)QKV_N * HDIM];             // W_attn^T
__device__ float g_wtp[(size_t)HDIM * HDIM];              // W_proj^T

__device__ __forceinline__ uint32_t f2tf32(float x) {
    uint32_t r;
    asm("cvt.rna.tf32.f32 %0, %1;" : "=r"(r) : "f"(x));
    return r;
}

// m16n8k8 tf32 MMA, fp32 accumulate
__device__ __forceinline__ void mma_tf32(float* c, const uint32_t* a, const uint32_t* b) {
    asm volatile(
        "mma.sync.aligned.m16n8k8.row.col.f32.tf32.tf32.f32 "
        "{%0,%1,%2,%3}, {%4,%5,%6,%7}, {%8,%9}, {%0,%1,%2,%3};"
        : "+f"(c[0]), "+f"(c[1]), "+f"(c[2]), "+f"(c[3])
        : "r"(a[0]), "r"(a[1]), "r"(a[2]), "r"(a[3]), "r"(b[0]), "r"(b[1]));
}

// ---------------------------------------------------------------------------
// Transpose: out[C][R] = in[R][C]
// ---------------------------------------------------------------------------
__global__ void transpose_kernel(const float* __restrict__ in, float* __restrict__ out,
                                 int R, int C)
{
    __shared__ float t[32][33];
    const int bx = blockIdx.x * 32;
    const int by = blockIdx.y * 32;
#pragma unroll
    for (int i = 0; i < 32; i += 8)
        t[threadIdx.y + i][threadIdx.x] = in[(size_t)(by + threadIdx.y + i) * C + bx + threadIdx.x];
    __syncthreads();
#pragma unroll
    for (int i = 0; i < 32; i += 8)
        out[(size_t)(bx + threadIdx.y + i) * R + by + threadIdx.x] = t[threadIdx.x][threadIdx.y + i];
}

// ---------------------------------------------------------------------------
// tf32 mma.sync GEMM (unchanged from R5): C = A @ Bt^T + bias
// ---------------------------------------------------------------------------
#define STAGE_FLOATS (2 * 128 * TPAD)
#define GEMM_SMEM    (2 * STAGE_FLOATS * 4)

__global__ __launch_bounds__(256)
void gemm_tf32_kernel(const float* __restrict__ A, const float* __restrict__ Bt,
                      const float* __restrict__ bias, float* __restrict__ C,
                      int M, int N, int K)
{
    extern __shared__ float sm[];
    const int tid    = threadIdx.x;
    const int lane   = tid & 31;
    const int wid    = tid >> 5;
    const int g      = lane >> 2;
    const int t      = lane & 3;
    const int warp_m = wid & 1;
    const int warp_n = wid >> 1;
    const int m0     = blockIdx.y << 7;
    const int n0     = blockIdx.x << 7;

    const float* Ap = A  + (size_t)m0 * K;
    const float* Bp = Bt + (size_t)n0 * K;

    float acc[4][4][4];
#pragma unroll
    for (int mt = 0; mt < 4; mt++)
#pragma unroll
        for (int nt = 0; nt < 4; nt++)
#pragma unroll
            for (int k = 0; k < 4; k++) acc[mt][nt][k] = 0.0f;

    float2 bv[4];
#pragma unroll
    for (int nt = 0; nt < 4; nt++)
        bv[nt] = *(const float2*)(bias + n0 + warp_n * 32 + nt * 8 + 2 * t);

    const int nchunks = K >> 5;

#pragma unroll
    for (int i = 0; i < 4; i++) {
        const int slot = tid + (i << 8);
        const int r    = slot >> 3;
        const int c4   = (slot & 7) << 2;
        float4 va = *(const float4*)(Ap + (size_t)r * K + c4);
        float4 vb = *(const float4*)(Bp + (size_t)r * K + c4);
        uint4 wa, wb;
        wa.x = f2tf32(va.x); wa.y = f2tf32(va.y); wa.z = f2tf32(va.z); wa.w = f2tf32(va.w);
        wb.x = f2tf32(vb.x); wb.y = f2tf32(vb.y); wb.z = f2tf32(vb.z); wb.w = f2tf32(vb.w);
        *(uint4*)(sm + r * TPAD + c4)              = wa;
        *(uint4*)(sm + 128 * TPAD + r * TPAD + c4) = wb;
    }
    __syncthreads();

    for (int c = 0; c < nchunks; ++c) {
        const int s = c & 1;
        const bool has_next = (c + 1) < nchunks;

        float4 pa[4], pb[4];
        if (has_next) {
            const int kcn = (c + 1) << 5;
#pragma unroll
            for (int i = 0; i < 4; i++) {
                const int slot = tid + (i << 8);
                const int r    = slot >> 3;
                const int c4   = (slot & 7) << 2;
                pa[i] = *(const float4*)(Ap + (size_t)r * K + kcn + c4);
                pb[i] = *(const float4*)(Bp + (size_t)r * K + kcn + c4);
            }
        }

        const float* sA = sm + s * STAGE_FLOATS;
        const float* sB = sA + 128 * TPAD;
#pragma unroll
        for (int ks = 0; ks < 4; ks++) {
            const int kof = ks * 8 + t;
            uint32_t afr[4][4], bfr[4][2];
#pragma unroll
            for (int mt = 0; mt < 4; mt++) {
                const int rb = (warp_m * 64 + mt * 16 + g) * TPAD + kof;
                afr[mt][0] = __float_as_uint(sA[rb]);
                afr[mt][1] = __float_as_uint(sA[rb + 8 * TPAD]);
                afr[mt][2] = __float_as_uint(sA[rb + 4]);
                afr[mt][3] = __float_as_uint(sA[rb + 8 * TPAD + 4]);
            }
#pragma unroll
            for (int nt = 0; nt < 4; nt++) {
                const int nb = (warp_n * 32 + nt * 8 + g) * TPAD + kof;
                bfr[nt][0] = __float_as_uint(sB[nb]);
                bfr[nt][1] = __float_as_uint(sB[nb + 4]);
            }
#pragma unroll
            for (int mt = 0; mt < 4; mt++)
#pragma unroll
                for (int nt = 0; nt < 4; nt++)
                    mma_tf32(acc[mt][nt], afr[mt], bfr[nt]);
        }

        if (has_next) {
            float* dA = sm + (s ^ 1) * STAGE_FLOATS;
            float* dB = dA + 128 * TPAD;
#pragma unroll
            for (int i = 0; i < 4; i++) {
                const int slot = tid + (i << 8);
                const int r    = slot >> 3;
                const int c4   = (slot & 7) << 2;
                uint4 wa, wb;
                wa.x = f2tf32(pa[i].x); wa.y = f2tf32(pa[i].y);
                wa.z = f2tf32(pa[i].z); wa.w = f2tf32(pa[i].w);
                wb.x = f2tf32(pb[i].x); wb.y = f2tf32(pb[i].y);
                wb.z = f2tf32(pb[i].z); wb.w = f2tf32(pb[i].w);
                *(uint4*)(dA + r * TPAD + c4) = wa;
                *(uint4*)(dB + r * TPAD + c4) = wb;
            }
        }
        __syncthreads();
    }

#pragma unroll
    for (int mt = 0; mt < 4; mt++) {
        const int row0 = m0 + warp_m * 64 + mt * 16 + g;
#pragma unroll
        for (int nt = 0; nt < 4; nt++) {
            const int col = n0 + warp_n * 32 + nt * 8 + 2 * t;
            float2 v0, v1;
            v0.x = acc[mt][nt][0] + bv[nt].x;
            v0.y = acc[mt][nt][1] + bv[nt].y;
            v1.x = acc[mt][nt][2] + bv[nt].x;
            v1.y = acc[mt][nt][3] + bv[nt].y;
            *(float2*)(C + (size_t)row0 * N + col)       = v0;
            *(float2*)(C + (size_t)(row0 + 8) * N + col) = v1;
        }
    }
}

// ---------------------------------------------------------------------------
// Flash attention, tf32 mma.sync. q-tile 128 (8 warps x 16 rows), kv-tile 64.
// Softmax fully warp-local; P redistributed to A-fragments via quad shuffles.
// Head split is the reference's plain reshape:
//   Qh[q][d] = qkv[b][nh*128 + q/16][(q%16)*128 + d] (+2048 K, +4096 V)
// ---------------------------------------------------------------------------
__global__ __launch_bounds__(256, 1)
void attn_mma_kernel(float* __restrict__ att_out)
{
    extern __shared__ float sm[];
    float* Qs = sm;

    const int qt  = 15 - blockIdx.x;     // heavy tiles first
    const int nh  = blockIdx.y;
    const int b   = blockIdx.z;
    const int q0  = qt << 7;
    const int tid = threadIdx.x;
    const int lane = tid & 31;
    const int wid  = tid >> 5;
    const int g    = lane >> 2;
    const int t    = lane & 3;
    const int qbase = lane & 28;         // quad base lane

    const size_t base_bh = ((size_t)b * S_LEN + (size_t)nh * HD) * QKV_N;

    // ---- Q fill (128 x 128, tf32, stride 132) ----
#pragma unroll
    for (int i = 0; i < 16; i++) {
        const int slot = tid + (i << 8);
        const int r  = slot >> 5;
        const int c4 = (slot & 31) << 2;
        const int qg = q0 + r;
        const float* p = g_qkv + base_bh + (size_t)(qg >> 4) * QKV_N + ((qg & 15) << 7) + c4;
        float4 v = *(const float4*)p;
        uint4 w;
        w.x = f2tf32(v.x); w.y = f2tf32(v.y); w.z = f2tf32(v.z); w.w = f2tf32(v.w);
        *(uint4*)(Qs + r * AT_STR + c4) = w;
    }
    // ---- K/V tile 0 fill into stage 0 ----
    {
        float* K0 = sm + ATT_Q_FLOATS;
        float* V0 = K0 + ATT_KV_FLOATS;
#pragma unroll
        for (int i = 0; i < 8; i++) {
            const int slot = tid + (i << 8);
            const int r  = slot >> 5;
            const int c4 = (slot & 31) << 2;
            const float* p = g_qkv + base_bh + (size_t)(r >> 4) * QKV_N + ((r & 15) << 7) + c4;
            float4 kv = *(const float4*)(p + HDIM);
            float4 vv = *(const float4*)(p + 2 * HDIM);
            uint4 wk, wv;
            wk.x = f2tf32(kv.x); wk.y = f2tf32(kv.y); wk.z = f2tf32(kv.z); wk.w = f2tf32(kv.w);
            wv.x = f2tf32(vv.x); wv.y = f2tf32(vv.y); wv.z = f2tf32(vv.z); wv.w = f2tf32(vv.w);
            *(uint4*)(K0 + r * AT_STR + c4) = wk;
            *(uint4*)(V0 + r * AT_STR + c4) = wv;
        }
    }
    __syncthreads();

    float O[16][4];
#pragma unroll
    for (int nt = 0; nt < 16; nt++)
#pragma unroll
        for (int k = 0; k < 4; k++) O[nt][k] = 0.0f;

    float m_run[2] = {-1e30f, -1e30f};
    float l_run[2] = {0.0f, 0.0f};

    const int nkt  = (q0 + 128) >> 6;
    const int arow = (wid << 4) + g;

    for (int kt = 0; kt < nkt; kt++) {
        const int s  = kt & 1;
        const int k0 = kt << 6;
        const float* Kc = sm + ATT_Q_FLOATS + s * 2 * ATT_KV_FLOATS;
        const float* Vc = Kc + ATT_KV_FLOATS;
        float* Kn = sm + ATT_Q_FLOATS + (s ^ 1) * 2 * ATT_KV_FLOATS;
        float* Vn = Kn + ATT_KV_FLOATS;
        const bool pre = (kt + 1) < nkt;
        const int k0n  = (kt + 1) << 6;

        // prefetch next K tile (global -> regs)
        float4 pk[8];
        if (pre) {
#pragma unroll
            for (int i = 0; i < 8; i++) {
                const int slot = tid + (i << 8);
                const int r  = slot >> 5;
                const int c4 = (slot & 31) << 2;
                const int kg = k0n + r;
                pk[i] = *(const float4*)(g_qkv + base_bh + (size_t)(kg >> 4) * QKV_N +
                                         ((kg & 15) << 7) + HDIM + c4);
            }
        }

        // ---- S = Q K^T (16x64 per warp) ----
        float sacc[8][4];
#pragma unroll
        for (int nt = 0; nt < 8; nt++)
#pragma unroll
            for (int k = 0; k < 4; k++) sacc[nt][k] = 0.0f;

#pragma unroll
        for (int ks = 0; ks < 16; ks++) {
            const int kof = (ks << 3) + t;
            uint32_t a[4];
            a[0] = __float_as_uint(Qs[arow * AT_STR + kof]);
            a[1] = __float_as_uint(Qs[(arow + 8) * AT_STR + kof]);
            a[2] = __float_as_uint(Qs[arow * AT_STR + kof + 4]);
            a[3] = __float_as_uint(Qs[(arow + 8) * AT_STR + kof + 4]);
#pragma unroll
            for (int nt = 0; nt < 8; nt++) {
                uint32_t bfr[2];
                bfr[0] = __float_as_uint(Kc[(g + nt * 8) * AT_STR + kof]);
                bfr[1] = __float_as_uint(Kc[(g + nt * 8) * AT_STR + kof + 4]);
                mma_tf32(sacc[nt], a, bfr);
            }
        }

        // store prefetched K into next stage
        if (pre) {
#pragma unroll
            for (int i = 0; i < 8; i++) {
                const int slot = tid + (i << 8);
                const int r  = slot >> 5;
                const int c4 = (slot & 31) << 2;
                uint4 w;
                w.x = f2tf32(pk[i].x); w.y = f2tf32(pk[i].y);
                w.z = f2tf32(pk[i].z); w.w = f2tf32(pk[i].w);
                *(uint4*)(Kn + r * AT_STR + c4) = w;
            }
        }

        // prefetch next V tile
        float4 pv[8];
        if (pre) {
#pragma unroll
            for (int i = 0; i < 8; i++) {
                const int slot = tid + (i << 8);
                const int r  = slot >> 5;
                const int c4 = (slot & 31) << 2;
                const int kg = k0n + r;
                pv[i] = *(const float4*)(g_qkv + base_bh + (size_t)(kg >> 4) * QKV_N +
                                         ((kg & 15) << 7) + 2 * HDIM + c4);
            }
        }

        // ---- online softmax (warp-local; rows g and g+8) ----
        const bool crossing = (k0 + 63) > (q0 + (wid << 4));
        float pexp[2][8][2];
        float corr[2];
#pragma unroll
        for (int r = 0; r < 2; r++) {
            const int qg = q0 + (wid << 4) + g + 8 * r;
            float rm = -1e30f;
#pragma unroll
            for (int nt = 0; nt < 8; nt++) {
#pragma unroll
                for (int j = 0; j < 2; j++) {
                    float v = sacc[nt][2 * r + j] * SCALE;
                    if (crossing && (k0 + nt * 8 + 2 * t + j) > qg) v = -1e9f;
                    sacc[nt][2 * r + j] = v;
                    rm = fmaxf(rm, v);
                }
            }
            rm = fmaxf(rm, __shfl_xor_sync(0xffffffffu, rm, 1));
            rm = fmaxf(rm, __shfl_xor_sync(0xffffffffu, rm, 2));

            const float mn = fmaxf(m_run[r], rm);
            corr[r] = __expf(m_run[r] - mn);
            m_run[r] = mn;

            float rs = 0.0f;
#pragma unroll
            for (int nt = 0; nt < 8; nt++) {
#pragma unroll
                for (int j = 0; j < 2; j++) {
                    float p = __expf(sacc[nt][2 * r + j] - mn);
                    pexp[r][nt][j] = p;
                    rs += p;
                }
            }
            rs += __shfl_xor_sync(0xffffffffu, rs, 1);
            rs += __shfl_xor_sync(0xffffffffu, rs, 2);
            l_run[r] = l_run[r] * corr[r] + rs;
        }
#pragma unroll
        for (int nt = 0; nt < 16; nt++) {
            O[nt][0] *= corr[0]; O[nt][1] *= corr[0];
            O[nt][2] *= corr[1]; O[nt][3] *= corr[1];
        }

        // ---- O += P V : P A-frags via quad shuffles ----
        const int s0 = qbase + (t >> 1);
        const int s2 = s0 + 2;
        const bool odd = (t & 1);
#pragma unroll
        for (int ks = 0; ks < 8; ks++) {
            float x0 = __shfl_sync(0xffffffffu, pexp[0][ks][0], s0);
            float y0 = __shfl_sync(0xffffffffu, pexp[0][ks][1], s0);
            float x1 = __shfl_sync(0xffffffffu, pexp[1][ks][0], s0);
            float y1 = __shfl_sync(0xffffffffu, pexp[1][ks][1], s0);
            float x2 = __shfl_sync(0xffffffffu, pexp[0][ks][0], s2);
            float y2 = __shfl_sync(0xffffffffu, pexp[0][ks][1], s2);
            float x3 = __shfl_sync(0xffffffffu, pexp[1][ks][0], s2);
            float y3 = __shfl_sync(0xffffffffu, pexp[1][ks][1], s2);
            uint32_t a[4];
            a[0] = f2tf32(odd ? y0 : x0);
            a[1] = f2tf32(odd ? y1 : x1);
            a[2] = f2tf32(odd ? y2 : x2);
            a[3] = f2tf32(odd ? y3 : x3);
#pragma unroll
            for (int nt = 0; nt < 16; nt++) {
                uint32_t bfr[2];
                bfr[0] = __float_as_uint(Vc[(ks * 8 + t) * AT_STR + nt * 8 + g]);
                bfr[1] = __float_as_uint(Vc[(ks * 8 + t + 4) * AT_STR + nt * 8 + g]);
                mma_tf32(O[nt], a, bfr);
            }
        }

        // store prefetched V into next stage
        if (pre) {
#pragma unroll
            for (int i = 0; i < 8; i++) {
                const int slot = tid + (i << 8);
                const int r  = slot >> 5;
                const int c4 = (slot & 31) << 2;
                uint4 w;
                w.x = f2tf32(pv[i].x); w.y = f2tf32(pv[i].y);
                w.z = f2tf32(pv[i].z); w.w = f2tf32(pv[i].w);
                *(uint4*)(Vn + r * AT_STR + c4) = w;
            }
        }
        __syncthreads();
    }

    // ---- epilogue: normalize, write [b][q][nh*128 + d] ----
#pragma unroll
    for (int r = 0; r < 2; r++) {
        const float inv = 1.0f / l_run[r];
        const int qg = q0 + (wid << 4) + g + 8 * r;
        float* op = att_out + ((size_t)b * S_LEN + qg) * HDIM + nh * HD;
#pragma unroll
        for (int nt = 0; nt < 16; nt++) {
            float2 v;
            v.x = O[nt][2 * r]     * inv;
            v.y = O[nt][2 * r + 1] * inv;
            *(float2*)(op + nt * 8 + 2 * t) = v;
        }
    }
}

// ---------------------------------------------------------------------------
// Launch
// ---------------------------------------------------------------------------
extern "C" void kernel_launch(void* const* d_in, const int* in_sizes, int n_in,
                              void* d_out, int out_size)
{
    const float* hidden = (const float*)d_in[0];
    const float* W_attn = (const float*)d_in[2];
    const float* b_attn = (const float*)d_in[3];
    const float* W_proj = (const float*)d_in[4];
    const float* b_proj = (const float*)d_in[5];
    float* out = (float*)d_out;

    float *qkv, *att, *wta, *wtp;
    cudaGetSymbolAddress((void**)&qkv, g_qkv);
    cudaGetSymbolAddress((void**)&att, g_att);
    cudaGetSymbolAddress((void**)&wta, g_wta);
    cudaGetSymbolAddress((void**)&wtp, g_wtp);

    const int M = BATCH * S_LEN;   // 4096

    // 0) Transpose weights to K-major
    {
        dim3 blk(32, 8);
        transpose_kernel<<<dim3(QKV_N / 32, HDIM / 32), blk>>>(W_attn, wta, HDIM, QKV_N);
        transpose_kernel<<<dim3(HDIM / 32, HDIM / 32), blk>>>(W_proj, wtp, HDIM, HDIM);
    }

    cudaFuncSetAttribute(gemm_tf32_kernel,
                         cudaFuncAttributeMaxDynamicSharedMemorySize, GEMM_SMEM);

    // 1) QKV projection (tf32 mma.sync)
    gemm_tf32_kernel<<<dim3(QKV_N / 128, M / 128), 256, GEMM_SMEM>>>(
        hidden, wta, b_attn, qkv, M, QKV_N, HDIM);

    // 2) Attention (tf32 mma.sync flash)
    {
        cudaFuncSetAttribute(attn_mma_kernel,
                             cudaFuncAttributeMaxDynamicSharedMemorySize, ATT_SMEM_B);
        dim3 grid(S_LEN / 128, NHEADS, BATCH);
        attn_mma_kernel<<<grid, 256, ATT_SMEM_B>>>(att);
    }

    // 3) Output projection (tf32 mma.sync)
    gemm_tf32_kernel<<<dim3(HDIM / 128, M / 128), 256, GEMM_SMEM>>>(
        att, wtp, b_proj, out, M, HDIM, HDIM);
}

// round 8
// speedup vs baseline: 3.2441x; 1.3189x over previous
#include <cuda_runtime.h>
#include <cstdint>
#include <cstddef>

// Problem constants
#define S_LEN   2048
#define HDIM    2048
#define NHEADS  16
#define HD      128
#define BATCH   2
#define QKV_N   6144
#define SCALE   0.08838834764831845f

// Attention smem: Q[128*132], K0,V0,K1,V1 each 64*132
#define AT_STR        132
#define ATT_Q_FLOATS  (128 * AT_STR)
#define ATT_KV_FLOATS (64 * AT_STR)
#define ATT_SMEM_B    ((ATT_Q_FLOATS + 4 * ATT_KV_FLOATS) * 4)   // 202752

// GEMM smem: 4 stages x (A 128x20 + B 128x20) floats
#define GSTR          20
#define GSTAGE_FLOATS (2 * 128 * GSTR)       // 5120
#define GEMM_SMEM     (4 * GSTAGE_FLOATS * 4) // 81920

// Scratch (device globals — allocation-free)
__device__ float g_hid[(size_t)BATCH * S_LEN * HDIM];     // tf32-rounded hidden
__device__ float g_qkv[(size_t)BATCH * S_LEN * QKV_N];    // tf32-rounded qkv
__device__ float g_att[(size_t)BATCH * S_LEN * HDIM];     // tf32-rounded attention out
__device__ float g_wta[(size_t)QKV_N * HDIM];             // W_attn^T (rounded)
__device__ float g_wtp[(size_t)HDIM * HDIM];              // W_proj^T (rounded)

__device__ __forceinline__ uint32_t smem_u32(const void* p) {
    uint32_t a;
    asm("{ .reg .u64 t; cvta.to.shared.u64 t, %1; cvt.u32.u64 %0, t; }" : "=r"(a) : "l"(p));
    return a;
}
__device__ __forceinline__ uint32_t f2tf32(float x) {
    uint32_t r;
    asm("cvt.rna.tf32.f32 %0, %1;" : "=r"(r) : "f"(x));
    return r;
}
__device__ __forceinline__ float roundtf(float x) { return __uint_as_float(f2tf32(x)); }

__device__ __forceinline__ void cp16(uint32_t dst, const void* src) {
    asm volatile("cp.async.cg.shared.global [%0], [%1], 16;" :: "r"(dst), "l"(src));
}
#define CP_COMMIT() asm volatile("cp.async.commit_group;" ::: "memory")
#define CP_WAIT2()  asm volatile("cp.async.wait_group 2;" ::: "memory")
#define CP_WAIT0()  asm volatile("cp.async.wait_group 0;" ::: "memory")

// m16n8k8 tf32 MMA, fp32 accumulate
__device__ __forceinline__ void mma_tf32(float* c, const uint32_t* a, const uint32_t* b) {
    asm volatile(
        "mma.sync.aligned.m16n8k8.row.col.f32.tf32.tf32.f32 "
        "{%0,%1,%2,%3}, {%4,%5,%6,%7}, {%8,%9}, {%0,%1,%2,%3};"
        : "+f"(c[0]), "+f"(c[1]), "+f"(c[2]), "+f"(c[3])
        : "r"(a[0]), "r"(a[1]), "r"(a[2]), "r"(a[3]), "r"(b[0]), "r"(b[1]));
}

// ---------------------------------------------------------------------------
// Round fp32 -> tf32(rna) elementwise
// ---------------------------------------------------------------------------
__global__ void round_tf32_kernel(const float* __restrict__ in, float* __restrict__ out)
{
    const size_t i = ((size_t)blockIdx.x * blockDim.x + threadIdx.x) * 4;
    float4 v = *(const float4*)(in + i);
    v.x = roundtf(v.x); v.y = roundtf(v.y); v.z = roundtf(v.z); v.w = roundtf(v.w);
    *(float4*)(out + i) = v;
}

// ---------------------------------------------------------------------------
// Transpose + round: out[C][R] = tf32(in[R][C])
// ---------------------------------------------------------------------------
__global__ void transpose_kernel(const float* __restrict__ in, float* __restrict__ out,
                                 int R, int C)
{
    __shared__ float t[32][33];
    const int bx = blockIdx.x * 32;
    const int by = blockIdx.y * 32;
#pragma unroll
    for (int i = 0; i < 32; i += 8)
        t[threadIdx.y + i][threadIdx.x] =
            in[(size_t)(by + threadIdx.y + i) * C + bx + threadIdx.x];
    __syncthreads();
#pragma unroll
    for (int i = 0; i < 32; i += 8)
        out[(size_t)(bx + threadIdx.y + i) * R + by + threadIdx.x] =
            roundtf(t[threadIdx.x][threadIdx.y + i]);
}

// ---------------------------------------------------------------------------
// tf32 mma.sync GEMM, cp.async 4-stage: C = A @ Bt^T + bias
// A, Bt pre-rounded to tf32. CTA 128x128, 256 thr, warp 64x32, K-chunk 16.
// round_out: round C to tf32 (for intermediates consumed by later mma).
// ---------------------------------------------------------------------------
__global__ __launch_bounds__(256, 2)
void gemm_tf32_kernel(const float* __restrict__ A, const float* __restrict__ Bt,
                      const float* __restrict__ bias, float* __restrict__ C,
                      int M, int N, int K, int round_out)
{
    extern __shared__ float sm[];
    const uint32_t smb = smem_u32(sm);
    const int tid    = threadIdx.x;
    const int lane   = tid & 31;
    const int wid    = tid >> 5;
    const int g      = lane >> 2;
    const int t      = lane & 3;
    const int warp_m = wid & 1;
    const int warp_n = wid >> 1;
    const int m0     = blockIdx.y << 7;
    const int n0     = blockIdx.x << 7;

    const float* Ap = A  + (size_t)m0 * K;
    const float* Bp = Bt + (size_t)n0 * K;

    const int nchunks = K >> 4;
    const int fr  = tid >> 2;           // fill row 0..63 (x2)
    const int fc4 = (tid & 3) << 2;     // fill col 0,4,8,12

    // fill stage s with chunk c (both A and B; 2 rows per thread each)
    auto fill = [&](int c, int s) {
        if (c < nchunks) {
            const int kc = c << 4;
            const uint32_t sa = smb + (uint32_t)s * GSTAGE_FLOATS * 4;
#pragma unroll
            for (int i = 0; i < 2; i++) {
                const int r = fr + (i << 6);
                cp16(sa + (uint32_t)(r * GSTR + fc4) * 4,
                     Ap + (size_t)r * K + kc + fc4);
                cp16(sa + (uint32_t)((128 * GSTR) + r * GSTR + fc4) * 4,
                     Bp + (size_t)r * K + kc + fc4);
            }
        }
        CP_COMMIT();
    };

    float acc[4][4][4];
#pragma unroll
    for (int mt = 0; mt < 4; mt++)
#pragma unroll
        for (int nt = 0; nt < 4; nt++)
#pragma unroll
            for (int k = 0; k < 4; k++) acc[mt][nt][k] = 0.0f;

    float2 bv[4];
#pragma unroll
    for (int nt = 0; nt < 4; nt++)
        bv[nt] = *(const float2*)(bias + n0 + warp_n * 32 + nt * 8 + 2 * t);

    fill(0, 0); fill(1, 1); fill(2, 2);

    for (int c = 0; c < nchunks; ++c) {
        const int s = c & 3;
        CP_WAIT2();
        __syncthreads();
        fill(c + 3, (c + 3) & 3);

        const float* sA = sm + s * GSTAGE_FLOATS;
        const float* sB = sA + 128 * GSTR;
#pragma unroll
        for (int ks = 0; ks < 2; ks++) {
            const int kof = ks * 8 + t;
            uint32_t afr[4][4], bfr[4][2];
#pragma unroll
            for (int mt = 0; mt < 4; mt++) {
                const int rb = (warp_m * 64 + mt * 16 + g) * GSTR + kof;
                afr[mt][0] = __float_as_uint(sA[rb]);
                afr[mt][1] = __float_as_uint(sA[rb + 8 * GSTR]);
                afr[mt][2] = __float_as_uint(sA[rb + 4]);
                afr[mt][3] = __float_as_uint(sA[rb + 8 * GSTR + 4]);
            }
#pragma unroll
            for (int nt = 0; nt < 4; nt++) {
                const int nb = (warp_n * 32 + nt * 8 + g) * GSTR + kof;
                bfr[nt][0] = __float_as_uint(sB[nb]);
                bfr[nt][1] = __float_as_uint(sB[nb + 4]);
            }
#pragma unroll
            for (int mt = 0; mt < 4; mt++)
#pragma unroll
                for (int nt = 0; nt < 4; nt++)
                    mma_tf32(acc[mt][nt], afr[mt], bfr[nt]);
        }
    }

#pragma unroll
    for (int mt = 0; mt < 4; mt++) {
        const int row0 = m0 + warp_m * 64 + mt * 16 + g;
#pragma unroll
        for (int nt = 0; nt < 4; nt++) {
            const int col = n0 + warp_n * 32 + nt * 8 + 2 * t;
            float2 v0, v1;
            v0.x = acc[mt][nt][0] + bv[nt].x;
            v0.y = acc[mt][nt][1] + bv[nt].y;
            v1.x = acc[mt][nt][2] + bv[nt].x;
            v1.y = acc[mt][nt][3] + bv[nt].y;
            if (round_out) {
                v0.x = roundtf(v0.x); v0.y = roundtf(v0.y);
                v1.x = roundtf(v1.x); v1.y = roundtf(v1.y);
            }
            *(float2*)(C + (size_t)row0 * N + col)       = v0;
            *(float2*)(C + (size_t)(row0 + 8) * N + col) = v1;
        }
    }
}

// ---------------------------------------------------------------------------
// Flash attention, tf32 mma.sync, cp.async fills (qkv pre-rounded).
// q-tile 128 (8 warps x 16 rows), kv-tile 64, warp-local softmax.
// ---------------------------------------------------------------------------
__global__ __launch_bounds__(256, 1)
void attn_mma_kernel(float* __restrict__ att_out)
{
    extern __shared__ float sm[];
    float* Qs = sm;
    const uint32_t smb = smem_u32(sm);

    const int qt  = 15 - blockIdx.x;     // heavy tiles first
    const int nh  = blockIdx.y;
    const int b   = blockIdx.z;
    const int q0  = qt << 7;
    const int tid = threadIdx.x;
    const int lane = tid & 31;
    const int wid  = tid >> 5;
    const int g    = lane >> 2;
    const int t    = lane & 3;
    const int qbase = lane & 28;

    const size_t base_bh = ((size_t)b * S_LEN + (size_t)nh * HD) * QKV_N;
    const int fr  = tid >> 5;           // 0..7
    const int fc4 = (tid & 31) << 2;    // 0..124

    // ---- Q fill (cp.async, 16 rows per thread-slice) ----
#pragma unroll
    for (int i = 0; i < 16; i++) {
        const int r  = fr + (i << 3);
        const int qg = q0 + r;
        cp16(smb + (uint32_t)(r * AT_STR + fc4) * 4,
             g_qkv + base_bh + (size_t)(qg >> 4) * QKV_N + ((qg & 15) << 7) + fc4);
    }
    // ---- K/V tile 0 into stage 0 ----
    {
        const uint32_t k0b = smb + ATT_Q_FLOATS * 4;
        const uint32_t v0b = k0b + ATT_KV_FLOATS * 4;
#pragma unroll
        for (int i = 0; i < 8; i++) {
            const int r = fr + (i << 3);
            const float* p = g_qkv + base_bh + (size_t)(r >> 4) * QKV_N + ((r & 15) << 7) + fc4;
            cp16(k0b + (uint32_t)(r * AT_STR + fc4) * 4, p + HDIM);
            cp16(v0b + (uint32_t)(r * AT_STR + fc4) * 4, p + 2 * HDIM);
        }
    }
    CP_COMMIT();
    CP_WAIT0();
    __syncthreads();

    float O[16][4];
#pragma unroll
    for (int nt = 0; nt < 16; nt++)
#pragma unroll
        for (int k = 0; k < 4; k++) O[nt][k] = 0.0f;

    float m_run[2] = {-1e30f, -1e30f};
    float l_run[2] = {0.0f, 0.0f};

    const int nkt  = (q0 + 128) >> 6;
    const int arow = (wid << 4) + g;

    for (int kt = 0; kt < nkt; kt++) {
        const int s  = kt & 1;
        const int k0 = kt << 6;
        const float* Kc = sm + ATT_Q_FLOATS + s * 2 * ATT_KV_FLOATS;
        const float* Vc = Kc + ATT_KV_FLOATS;
        const bool pre = (kt + 1) < nkt;

        // issue cp.async fill for next K/V tile into the other stage
        if (pre) {
            const int k0n = (kt + 1) << 6;
            const uint32_t knb = smb + (ATT_Q_FLOATS + (s ^ 1) * 2 * ATT_KV_FLOATS) * 4;
            const uint32_t vnb = knb + ATT_KV_FLOATS * 4;
#pragma unroll
            for (int i = 0; i < 8; i++) {
                const int r  = fr + (i << 3);
                const int kg = k0n + r;
                const float* p = g_qkv + base_bh + (size_t)(kg >> 4) * QKV_N +
                                 ((kg & 15) << 7) + fc4;
                cp16(knb + (uint32_t)(r * AT_STR + fc4) * 4, p + HDIM);
                cp16(vnb + (uint32_t)(r * AT_STR + fc4) * 4, p + 2 * HDIM);
            }
            CP_COMMIT();
        }

        // ---- S = Q K^T (16x64 per warp) ----
        float sacc[8][4];
#pragma unroll
        for (int nt = 0; nt < 8; nt++)
#pragma unroll
            for (int k = 0; k < 4; k++) sacc[nt][k] = 0.0f;

#pragma unroll
        for (int ks = 0; ks < 16; ks++) {
            const int kof = (ks << 3) + t;
            uint32_t a[4];
            a[0] = __float_as_uint(Qs[arow * AT_STR + kof]);
            a[1] = __float_as_uint(Qs[(arow + 8) * AT_STR + kof]);
            a[2] = __float_as_uint(Qs[arow * AT_STR + kof + 4]);
            a[3] = __float_as_uint(Qs[(arow + 8) * AT_STR + kof + 4]);
#pragma unroll
            for (int nt = 0; nt < 8; nt++) {
                uint32_t bfr[2];
                bfr[0] = __float_as_uint(Kc[(g + nt * 8) * AT_STR + kof]);
                bfr[1] = __float_as_uint(Kc[(g + nt * 8) * AT_STR + kof + 4]);
                mma_tf32(sacc[nt], a, bfr);
            }
        }

        // ---- online softmax (warp-local; rows g and g+8) ----
        const bool crossing = (k0 + 63) > (q0 + (wid << 4));
        float pexp[2][8][2];
        float corr[2];
#pragma unroll
        for (int r = 0; r < 2; r++) {
            const int qg = q0 + (wid << 4) + g + 8 * r;
            float rm = -1e30f;
#pragma unroll
            for (int nt = 0; nt < 8; nt++) {
#pragma unroll
                for (int j = 0; j < 2; j++) {
                    float v = sacc[nt][2 * r + j] * SCALE;
                    if (crossing && (k0 + nt * 8 + 2 * t + j) > qg) v = -1e9f;
                    sacc[nt][2 * r + j] = v;
                    rm = fmaxf(rm, v);
                }
            }
            rm = fmaxf(rm, __shfl_xor_sync(0xffffffffu, rm, 1));
            rm = fmaxf(rm, __shfl_xor_sync(0xffffffffu, rm, 2));

            const float mn = fmaxf(m_run[r], rm);
            corr[r] = __expf(m_run[r] - mn);
            m_run[r] = mn;

            float rs = 0.0f;
#pragma unroll
            for (int nt = 0; nt < 8; nt++) {
#pragma unroll
                for (int j = 0; j < 2; j++) {
                    float p = __expf(sacc[nt][2 * r + j] - mn);
                    pexp[r][nt][j] = p;
                    rs += p;
                }
            }
            rs += __shfl_xor_sync(0xffffffffu, rs, 1);
            rs += __shfl_xor_sync(0xffffffffu, rs, 2);
            l_run[r] = l_run[r] * corr[r] + rs;
        }
#pragma unroll
        for (int nt = 0; nt < 16; nt++) {
            O[nt][0] *= corr[0]; O[nt][1] *= corr[0];
            O[nt][2] *= corr[1]; O[nt][3] *= corr[1];
        }

        // ---- O += P V : P A-frags via quad shuffles ----
        const int s0 = qbase + (t >> 1);
        const int s2 = s0 + 2;
        const bool odd = (t & 1);
#pragma unroll
        for (int ks = 0; ks < 8; ks++) {
            float x0 = __shfl_sync(0xffffffffu, pexp[0][ks][0], s0);
            float y0 = __shfl_sync(0xffffffffu, pexp[0][ks][1], s0);
            float x1 = __shfl_sync(0xffffffffu, pexp[1][ks][0], s0);
            float y1 = __shfl_sync(0xffffffffu, pexp[1][ks][1], s0);
            float x2 = __shfl_sync(0xffffffffu, pexp[0][ks][0], s2);
            float y2 = __shfl_sync(0xffffffffu, pexp[0][ks][1], s2);
            float x3 = __shfl_sync(0xffffffffu, pexp[1][ks][0], s2);
            float y3 = __shfl_sync(0xffffffffu, pexp[1][ks][1], s2);
            uint32_t a[4];
            a[0] = f2tf32(odd ? y0 : x0);
            a[1] = f2tf32(odd ? y1 : x1);
            a[2] = f2tf32(odd ? y2 : x2);
            a[3] = f2tf32(odd ? y3 : x3);
#pragma unroll
            for (int nt = 0; nt < 16; nt++) {
                uint32_t bfr[2];
                bfr[0] = __float_as_uint(Vc[(ks * 8 + t) * AT_STR + nt * 8 + g]);
                bfr[1] = __float_as_uint(Vc[(ks * 8 + t + 4) * AT_STR + nt * 8 + g]);
                mma_tf32(O[nt], a, bfr);
            }
        }

        CP_WAIT0();
        __syncthreads();
    }

    // ---- epilogue: normalize, round to tf32, write [b][q][nh*128 + d] ----
#pragma unroll
    for (int r = 0; r < 2; r++) {
        const float inv = 1.0f / l_run[r];
        const int qg = q0 + (wid << 4) + g + 8 * r;
        float* op = att_out + ((size_t)b * S_LEN + qg) * HDIM + nh * HD;
#pragma unroll
        for (int nt = 0; nt < 16; nt++) {
            float2 v;
            v.x = roundtf(O[nt][2 * r]     * inv);
            v.y = roundtf(O[nt][2 * r + 1] * inv);
            *(float2*)(op + nt * 8 + 2 * t) = v;
        }
    }
}

// ---------------------------------------------------------------------------
// Launch
// ---------------------------------------------------------------------------
extern "C" void kernel_launch(void* const* d_in, const int* in_sizes, int n_in,
                              void* d_out, int out_size)
{
    const float* hidden = (const float*)d_in[0];
    const float* W_attn = (const float*)d_in[2];
    const float* b_attn = (const float*)d_in[3];
    const float* W_proj = (const float*)d_in[4];
    const float* b_proj = (const float*)d_in[5];
    float* out = (float*)d_out;

    float *hid, *qkv, *att, *wta, *wtp;
    cudaGetSymbolAddress((void**)&hid, g_hid);
    cudaGetSymbolAddress((void**)&qkv, g_qkv);
    cudaGetSymbolAddress((void**)&att, g_att);
    cudaGetSymbolAddress((void**)&wta, g_wta);
    cudaGetSymbolAddress((void**)&wtp, g_wtp);

    const int M = BATCH * S_LEN;   // 4096

    // 0) Round hidden to tf32; transpose+round weights
    {
        const size_t n = (size_t)BATCH * S_LEN * HDIM;    // 8.4M
        round_tf32_kernel<<<(int)(n / 4 / 256), 256>>>(hidden, hid);
        dim3 blk(32, 8);
        transpose_kernel<<<dim3(QKV_N / 32, HDIM / 32), blk>>>(W_attn, wta, HDIM, QKV_N);
        transpose_kernel<<<dim3(HDIM / 32, HDIM / 32), blk>>>(W_proj, wtp, HDIM, HDIM);
    }

    cudaFuncSetAttribute(gemm_tf32_kernel,
                         cudaFuncAttributeMaxDynamicSharedMemorySize, GEMM_SMEM);

    // 1) QKV projection (output rounded to tf32 for attention)
    gemm_tf32_kernel<<<dim3(QKV_N / 128, M / 128), 256, GEMM_SMEM>>>(
        hid, wta, b_attn, qkv, M, QKV_N, HDIM, 1);

    // 2) Attention (tf32 mma.sync flash; epilogue rounds for proj)
    {
        cudaFuncSetAttribute(attn_mma_kernel,
                             cudaFuncAttributeMaxDynamicSharedMemorySize, ATT_SMEM_B);
        dim3 grid(S_LEN / 128, NHEADS, BATCH);
        attn_mma_kernel<<<grid, 256, ATT_SMEM_B>>>(att);
    }

    // 3) Output projection (full fp32 output)
    gemm_tf32_kernel<<<dim3(HDIM / 128, M / 128), 256, GEMM_SMEM>>>(
        att, wtp, b_proj, out, M, HDIM, HDIM, 0);
}

// round 9
// speedup vs baseline: 3.2976x; 1.0165x over previous
#include <cuda_runtime.h>
#include <cstdint>
#include <cstddef>

// Problem constants
#define S_LEN   2048
#define HDIM    2048
#define NHEADS  16
#define HD      128
#define BATCH   2
#define QKV_N   6144
#define SCALE   0.08838834764831845f

// Attention smem: Q[128*132], K0,V0,K1,V1 each 64*132
#define AT_STR        132
#define ATT_Q_FLOATS  (128 * AT_STR)
#define ATT_KV_FLOATS (64 * AT_STR)
#define ATT_SMEM_B    ((ATT_Q_FLOATS + 4 * ATT_KV_FLOATS) * 4)   // 202752

// GEMM smem: 4 stages x (A 128x20 + B 128x20) floats
#define GSTR          20
#define GSTAGE_FLOATS (2 * 128 * GSTR)       // 5120
#define GEMM_SMEM     (4 * GSTAGE_FLOATS * 4) // 81920

// Scratch (device globals — allocation-free)
__device__ float g_hid[(size_t)BATCH * S_LEN * HDIM];     // tf32-rounded hidden
__device__ float g_qkv[(size_t)BATCH * S_LEN * QKV_N];    // tf32-rounded qkv
__device__ float g_att[(size_t)BATCH * S_LEN * HDIM];     // tf32-rounded attention out
__device__ float g_wta[(size_t)QKV_N * HDIM];             // W_attn^T (rounded)
__device__ float g_wtp[(size_t)HDIM * HDIM];              // W_proj^T (rounded)

__device__ __forceinline__ uint32_t smem_u32(const void* p) {
    uint32_t a;
    asm("{ .reg .u64 t; cvta.to.shared.u64 t, %1; cvt.u32.u64 %0, t; }" : "=r"(a) : "l"(p));
    return a;
}
__device__ __forceinline__ uint32_t f2tf32(float x) {
    uint32_t r;
    asm("cvt.rna.tf32.f32 %0, %1;" : "=r"(r) : "f"(x));
    return r;
}
__device__ __forceinline__ float roundtf(float x) { return __uint_as_float(f2tf32(x)); }

__device__ __forceinline__ void cp16(uint32_t dst, const void* src) {
    asm volatile("cp.async.cg.shared.global [%0], [%1], 16;" :: "r"(dst), "l"(src));
}
#define CP_COMMIT() asm volatile("cp.async.commit_group;" ::: "memory")
#define CP_WAIT0()  asm volatile("cp.async.wait_group 0;" ::: "memory")

// m16n8k8 tf32 MMA, fp32 accumulate
__device__ __forceinline__ void mma_tf32(float* c, const uint32_t* a, const uint32_t* b) {
    asm volatile(
        "mma.sync.aligned.m16n8k8.row.col.f32.tf32.tf32.f32 "
        "{%0,%1,%2,%3}, {%4,%5,%6,%7}, {%8,%9}, {%0,%1,%2,%3};"
        : "+f"(c[0]), "+f"(c[1]), "+f"(c[2]), "+f"(c[3])
        : "r"(a[0]), "r"(a[1]), "r"(a[2]), "r"(a[3]), "r"(b[0]), "r"(b[1]));
}

// ---------------------------------------------------------------------------
// Round fp32 -> tf32(rna) elementwise
// ---------------------------------------------------------------------------
__global__ void round_tf32_kernel(const float* __restrict__ in, float* __restrict__ out)
{
    const size_t i = ((size_t)blockIdx.x * blockDim.x + threadIdx.x) * 4;
    float4 v = *(const float4*)(in + i);
    v.x = roundtf(v.x); v.y = roundtf(v.y); v.z = roundtf(v.z); v.w = roundtf(v.w);
    *(float4*)(out + i) = v;
}

// ---------------------------------------------------------------------------
// Transpose + round: out[C][R] = tf32(in[R][C])
// ---------------------------------------------------------------------------
__global__ void transpose_kernel(const float* __restrict__ in, float* __restrict__ out,
                                 int R, int C)
{
    __shared__ float t[32][33];
    const int bx = blockIdx.x * 32;
    const int by = blockIdx.y * 32;
#pragma unroll
    for (int i = 0; i < 32; i += 8)
        t[threadIdx.y + i][threadIdx.x] =
            in[(size_t)(by + threadIdx.y + i) * C + bx + threadIdx.x];
    __syncthreads();
#pragma unroll
    for (int i = 0; i < 32; i += 8)
        out[(size_t)(bx + threadIdx.y + i) * R + by + threadIdx.x] =
            roundtf(t[threadIdx.x][threadIdx.y + i]);
}

// ---------------------------------------------------------------------------
// tf32 mma.sync GEMM, cp.async 4-stage, PAIR-CHUNK barriers (one sync per 32 K).
// C = A @ Bt^T + bias. A, Bt pre-rounded. CTA 128x128, 256 thr, warp 64x32.
// While pair p computes on its 2 stages, fills for pair p+1 land in the other 2.
// ---------------------------------------------------------------------------
__global__ __launch_bounds__(256, 2)
void gemm_tf32_kernel(const float* __restrict__ A, const float* __restrict__ Bt,
                      const float* __restrict__ bias, float* __restrict__ C,
                      int M, int N, int K, int round_out)
{
    extern __shared__ float sm[];
    const uint32_t smb = smem_u32(sm);
    const int tid    = threadIdx.x;
    const int lane   = tid & 31;
    const int wid    = tid >> 5;
    const int g      = lane >> 2;
    const int t      = lane & 3;
    const int warp_m = wid & 1;
    const int warp_n = wid >> 1;
    const int m0     = blockIdx.y << 7;
    const int n0     = blockIdx.x << 7;

    const float* Ap = A  + (size_t)m0 * K;
    const float* Bp = Bt + (size_t)n0 * K;

    const int nchunks = K >> 4;
    const int npairs  = nchunks >> 1;
    const int fr  = tid >> 2;           // fill row 0..63 (x2)
    const int fc4 = (tid & 3) << 2;     // fill col 0,4,8,12

    // fill stage s with chunk c (A and B; 2 rows each); one commit per chunk
    auto fill = [&](int c, int s) {
        if (c < nchunks) {
            const int kc = c << 4;
            const uint32_t sa = smb + (uint32_t)s * GSTAGE_FLOATS * 4;
#pragma unroll
            for (int i = 0; i < 2; i++) {
                const int r = fr + (i << 6);
                cp16(sa + (uint32_t)(r * GSTR + fc4) * 4,
                     Ap + (size_t)r * K + kc + fc4);
                cp16(sa + (uint32_t)((128 * GSTR) + r * GSTR + fc4) * 4,
                     Bp + (size_t)r * K + kc + fc4);
            }
        }
        CP_COMMIT();
    };

    float acc[4][4][4];
#pragma unroll
    for (int mt = 0; mt < 4; mt++)
#pragma unroll
        for (int nt = 0; nt < 4; nt++)
#pragma unroll
            for (int k = 0; k < 4; k++) acc[mt][nt][k] = 0.0f;

    float2 bv[4];
#pragma unroll
    for (int nt = 0; nt < 4; nt++)
        bv[nt] = *(const float2*)(bias + n0 + warp_n * 32 + nt * 8 + 2 * t);

    // prologue: fill pair 0 (stages 0,1)
    fill(0, 0); fill(1, 1);

    for (int p = 0; p < npairs; ++p) {
        const int c0 = p << 1;
        CP_WAIT0();           // this pair's two fills have landed
        __syncthreads();      // all warps done reading the other half
        // issue fills for pair p+1 into the other two stages
        fill(c0 + 2, (c0 + 2) & 3);
        fill(c0 + 3, (c0 + 3) & 3);

        // compute the pair: 2 chunks x 2 ks, no barrier inside -> wide ILP
#pragma unroll
        for (int half = 0; half < 2; ++half) {
            const int s = (c0 + half) & 3;
            const float* sA = sm + s * GSTAGE_FLOATS;
            const float* sB = sA + 128 * GSTR;
#pragma unroll
            for (int ks = 0; ks < 2; ks++) {
                const int kof = ks * 8 + t;
                uint32_t afr[4][4], bfr[4][2];
#pragma unroll
                for (int mt = 0; mt < 4; mt++) {
                    const int rb = (warp_m * 64 + mt * 16 + g) * GSTR + kof;
                    afr[mt][0] = __float_as_uint(sA[rb]);
                    afr[mt][1] = __float_as_uint(sA[rb + 8 * GSTR]);
                    afr[mt][2] = __float_as_uint(sA[rb + 4]);
                    afr[mt][3] = __float_as_uint(sA[rb + 8 * GSTR + 4]);
                }
#pragma unroll
                for (int nt = 0; nt < 4; nt++) {
                    const int nb = (warp_n * 32 + nt * 8 + g) * GSTR + kof;
                    bfr[nt][0] = __float_as_uint(sB[nb]);
                    bfr[nt][1] = __float_as_uint(sB[nb + 4]);
                }
#pragma unroll
                for (int mt = 0; mt < 4; mt++)
#pragma unroll
                    for (int nt = 0; nt < 4; nt++)
                        mma_tf32(acc[mt][nt], afr[mt], bfr[nt]);
            }
        }
    }

#pragma unroll
    for (int mt = 0; mt < 4; mt++) {
        const int row0 = m0 + warp_m * 64 + mt * 16 + g;
#pragma unroll
        for (int nt = 0; nt < 4; nt++) {
            const int col = n0 + warp_n * 32 + nt * 8 + 2 * t;
            float2 v0, v1;
            v0.x = acc[mt][nt][0] + bv[nt].x;
            v0.y = acc[mt][nt][1] + bv[nt].y;
            v1.x = acc[mt][nt][2] + bv[nt].x;
            v1.y = acc[mt][nt][3] + bv[nt].y;
            if (round_out) {
                v0.x = roundtf(v0.x); v0.y = roundtf(v0.y);
                v1.x = roundtf(v1.x); v1.y = roundtf(v1.y);
            }
            *(float2*)(C + (size_t)row0 * N + col)       = v0;
            *(float2*)(C + (size_t)(row0 + 8) * N + col) = v1;
        }
    }
}

// ---------------------------------------------------------------------------
// Flash attention, tf32 mma.sync, cp.async fills (qkv pre-rounded).
// q-tile 128 (8 warps x 16 rows), kv-tile 64, warp-local softmax.
// ---------------------------------------------------------------------------
__global__ __launch_bounds__(256, 1)
void attn_mma_kernel(float* __restrict__ att_out)
{
    extern __shared__ float sm[];
    float* Qs = sm;
    const uint32_t smb = smem_u32(sm);

    const int qt  = 15 - blockIdx.x;     // heavy tiles first
    const int nh  = blockIdx.y;
    const int b   = blockIdx.z;
    const int q0  = qt << 7;
    const int tid = threadIdx.x;
    const int lane = tid & 31;
    const int wid  = tid >> 5;
    const int g    = lane >> 2;
    const int t    = lane & 3;
    const int qbase = lane & 28;

    const size_t base_bh = ((size_t)b * S_LEN + (size_t)nh * HD) * QKV_N;
    const int fr  = tid >> 5;           // 0..7
    const int fc4 = (tid & 31) << 2;    // 0..124

    // ---- Q fill (cp.async) ----
#pragma unroll
    for (int i = 0; i < 16; i++) {
        const int r  = fr + (i << 3);
        const int qg = q0 + r;
        cp16(smb + (uint32_t)(r * AT_STR + fc4) * 4,
             g_qkv + base_bh + (size_t)(qg >> 4) * QKV_N + ((qg & 15) << 7) + fc4);
    }
    // ---- K/V tile 0 into stage 0 ----
    {
        const uint32_t k0b = smb + ATT_Q_FLOATS * 4;
        const uint32_t v0b = k0b + ATT_KV_FLOATS * 4;
#pragma unroll
        for (int i = 0; i < 8; i++) {
            const int r = fr + (i << 3);
            const float* p = g_qkv + base_bh + (size_t)(r >> 4) * QKV_N + ((r & 15) << 7) + fc4;
            cp16(k0b + (uint32_t)(r * AT_STR + fc4) * 4, p + HDIM);
            cp16(v0b + (uint32_t)(r * AT_STR + fc4) * 4, p + 2 * HDIM);
        }
    }
    CP_COMMIT();
    CP_WAIT0();
    __syncthreads();

    float O[16][4];
#pragma unroll
    for (int nt = 0; nt < 16; nt++)
#pragma unroll
        for (int k = 0; k < 4; k++) O[nt][k] = 0.0f;

    float m_run[2] = {-1e30f, -1e30f};
    float l_run[2] = {0.0f, 0.0f};

    const int nkt  = (q0 + 128) >> 6;
    const int arow = (wid << 4) + g;

    for (int kt = 0; kt < nkt; kt++) {
        const int s  = kt & 1;
        const int k0 = kt << 6;
        const float* Kc = sm + ATT_Q_FLOATS + s * 2 * ATT_KV_FLOATS;
        const float* Vc = Kc + ATT_KV_FLOATS;
        const bool pre = (kt + 1) < nkt;

        // issue cp.async fill for next K/V tile into the other stage
        if (pre) {
            const int k0n = (kt + 1) << 6;
            const uint32_t knb = smb + (ATT_Q_FLOATS + (s ^ 1) * 2 * ATT_KV_FLOATS) * 4;
            const uint32_t vnb = knb + ATT_KV_FLOATS * 4;
#pragma unroll
            for (int i = 0; i < 8; i++) {
                const int r  = fr + (i << 3);
                const int kg = k0n + r;
                const float* p = g_qkv + base_bh + (size_t)(kg >> 4) * QKV_N +
                                 ((kg & 15) << 7) + fc4;
                cp16(knb + (uint32_t)(r * AT_STR + fc4) * 4, p + HDIM);
                cp16(vnb + (uint32_t)(r * AT_STR + fc4) * 4, p + 2 * HDIM);
            }
            CP_COMMIT();
        }

        // ---- S = Q K^T (16x64 per warp) ----
        float sacc[8][4];
#pragma unroll
        for (int nt = 0; nt < 8; nt++)
#pragma unroll
            for (int k = 0; k < 4; k++) sacc[nt][k] = 0.0f;

#pragma unroll
        for (int ks = 0; ks < 16; ks++) {
            const int kof = (ks << 3) + t;
            uint32_t a[4];
            a[0] = __float_as_uint(Qs[arow * AT_STR + kof]);
            a[1] = __float_as_uint(Qs[(arow + 8) * AT_STR + kof]);
            a[2] = __float_as_uint(Qs[arow * AT_STR + kof + 4]);
            a[3] = __float_as_uint(Qs[(arow + 8) * AT_STR + kof + 4]);
#pragma unroll
            for (int nt = 0; nt < 8; nt++) {
                uint32_t bfr[2];
                bfr[0] = __float_as_uint(Kc[(g + nt * 8) * AT_STR + kof]);
                bfr[1] = __float_as_uint(Kc[(g + nt * 8) * AT_STR + kof + 4]);
                mma_tf32(sacc[nt], a, bfr);
            }
        }

        // ---- online softmax (warp-local; rows g and g+8) ----
        const bool crossing = (k0 + 63) > (q0 + (wid << 4));
        float pexp[2][8][2];
        float corr[2];
#pragma unroll
        for (int r = 0; r < 2; r++) {
            const int qg = q0 + (wid << 4) + g + 8 * r;
            float rm = -1e30f;
#pragma unroll
            for (int nt = 0; nt < 8; nt++) {
#pragma unroll
                for (int j = 0; j < 2; j++) {
                    float v = sacc[nt][2 * r + j] * SCALE;
                    if (crossing && (k0 + nt * 8 + 2 * t + j) > qg) v = -1e9f;
                    sacc[nt][2 * r + j] = v;
                    rm = fmaxf(rm, v);
                }
            }
            rm = fmaxf(rm, __shfl_xor_sync(0xffffffffu, rm, 1));
            rm = fmaxf(rm, __shfl_xor_sync(0xffffffffu, rm, 2));

            const float mn = fmaxf(m_run[r], rm);
            corr[r] = __expf(m_run[r] - mn);
            m_run[r] = mn;

            float rs = 0.0f;
#pragma unroll
            for (int nt = 0; nt < 8; nt++) {
#pragma unroll
                for (int j = 0; j < 2; j++) {
                    float p = __expf(sacc[nt][2 * r + j] - mn);
                    pexp[r][nt][j] = p;
                    rs += p;
                }
            }
            rs += __shfl_xor_sync(0xffffffffu, rs, 1);
            rs += __shfl_xor_sync(0xffffffffu, rs, 2);
            l_run[r] = l_run[r] * corr[r] + rs;
        }
#pragma unroll
        for (int nt = 0; nt < 16; nt++) {
            O[nt][0] *= corr[0]; O[nt][1] *= corr[0];
            O[nt][2] *= corr[1]; O[nt][3] *= corr[1];
        }

        // ---- O += P V : P A-frags via quad shuffles ----
        const int s0 = qbase + (t >> 1);
        const int s2 = s0 + 2;
        const bool odd = (t & 1);
#pragma unroll
        for (int ks = 0; ks < 8; ks++) {
            float x0 = __shfl_sync(0xffffffffu, pexp[0][ks][0], s0);
            float y0 = __shfl_sync(0xffffffffu, pexp[0][ks][1], s0);
            float x1 = __shfl_sync(0xffffffffu, pexp[1][ks][0], s0);
            float y1 = __shfl_sync(0xffffffffu, pexp[1][ks][1], s0);
            float x2 = __shfl_sync(0xffffffffu, pexp[0][ks][0], s2);
            float y2 = __shfl_sync(0xffffffffu, pexp[0][ks][1], s2);
            float x3 = __shfl_sync(0xffffffffu, pexp[1][ks][0], s2);
            float y3 = __shfl_sync(0xffffffffu, pexp[1][ks][1], s2);
            uint32_t a[4];
            a[0] = f2tf32(odd ? y0 : x0);
            a[1] = f2tf32(odd ? y1 : x1);
            a[2] = f2tf32(odd ? y2 : x2);
            a[3] = f2tf32(odd ? y3 : x3);
#pragma unroll
            for (int nt = 0; nt < 16; nt++) {
                uint32_t bfr[2];
                bfr[0] = __float_as_uint(Vc[(ks * 8 + t) * AT_STR + nt * 8 + g]);
                bfr[1] = __float_as_uint(Vc[(ks * 8 + t + 4) * AT_STR + nt * 8 + g]);
                mma_tf32(O[nt], a, bfr);
            }
        }

        CP_WAIT0();
        __syncthreads();
    }

    // ---- epilogue: normalize, round to tf32, write [b][q][nh*128 + d] ----
#pragma unroll
    for (int r = 0; r < 2; r++) {
        const float inv = 1.0f / l_run[r];
        const int qg = q0 + (wid << 4) + g + 8 * r;
        float* op = att_out + ((size_t)b * S_LEN + qg) * HDIM + nh * HD;
#pragma unroll
        for (int nt = 0; nt < 16; nt++) {
            float2 v;
            v.x = roundtf(O[nt][2 * r]     * inv);
            v.y = roundtf(O[nt][2 * r + 1] * inv);
            *(float2*)(op + nt * 8 + 2 * t) = v;
        }
    }
}

// ---------------------------------------------------------------------------
// Launch
// ---------------------------------------------------------------------------
extern "C" void kernel_launch(void* const* d_in, const int* in_sizes, int n_in,
                              void* d_out, int out_size)
{
    const float* hidden = (const float*)d_in[0];
    const float* W_attn = (const float*)d_in[2];
    const float* b_attn = (const float*)d_in[3];
    const float* W_proj = (const float*)d_in[4];
    const float* b_proj = (const float*)d_in[5];
    float* out = (float*)d_out;

    float *hid, *qkv, *att, *wta, *wtp;
    cudaGetSymbolAddress((void**)&hid, g_hid);
    cudaGetSymbolAddress((void**)&qkv, g_qkv);
    cudaGetSymbolAddress((void**)&att, g_att);
    cudaGetSymbolAddress((void**)&wta, g_wta);
    cudaGetSymbolAddress((void**)&wtp, g_wtp);

    const int M = BATCH * S_LEN;   // 4096

    // 0) Round hidden to tf32; transpose+round weights
    {
        const size_t n = (size_t)BATCH * S_LEN * HDIM;    // 8.4M
        round_tf32_kernel<<<(int)(n / 4 / 256), 256>>>(hidden, hid);
        dim3 blk(32, 8);
        transpose_kernel<<<dim3(QKV_N / 32, HDIM / 32), blk>>>(W_attn, wta, HDIM, QKV_N);
        transpose_kernel<<<dim3(HDIM / 32, HDIM / 32), blk>>>(W_proj, wtp, HDIM, HDIM);
    }

    cudaFuncSetAttribute(gemm_tf32_kernel,
                         cudaFuncAttributeMaxDynamicSharedMemorySize, GEMM_SMEM);

    // 1) QKV projection (output rounded to tf32 for attention)
    gemm_tf32_kernel<<<dim3(QKV_N / 128, M / 128), 256, GEMM_SMEM>>>(
        hid, wta, b_attn, qkv, M, QKV_N, HDIM, 1);

    // 2) Attention (tf32 mma.sync flash; epilogue rounds for proj)
    {
        cudaFuncSetAttribute(attn_mma_kernel,
                             cudaFuncAttributeMaxDynamicSharedMemorySize, ATT_SMEM_B);
        dim3 grid(S_LEN / 128, NHEADS, BATCH);
        attn_mma_kernel<<<grid, 256, ATT_SMEM_B>>>(att);
    }

    // 3) Output projection (full fp32 output)
    gemm_tf32_kernel<<<dim3(HDIM / 128, M / 128), 256, GEMM_SMEM>>>(
        att, wtp, b_proj, out, M, HDIM, HDIM, 0);
}

// round 10
// speedup vs baseline: 3.6786x; 1.1156x over previous
#include <cuda_runtime.h>
#include <cstdint>
#include <cstddef>

// Problem constants
#define S_LEN   2048
#define HDIM    2048
#define NHEADS  16
#define HD      128
#define BATCH   2
#define QKV_N   6144
#define SCALE   0.08838834764831845f

// Attention smem: Q[128*132], K0,V0,K1,V1 each 64*132
#define AT_STR        132
#define ATT_Q_FLOATS  (128 * AT_STR)
#define ATT_KV_FLOATS (64 * AT_STR)
#define ATT_SMEM_B    ((ATT_Q_FLOATS + 4 * ATT_KV_FLOATS) * 4)   // 202752

// GEMM smem: 4 stages x (A 128x20 + B 128x20) floats
#define GSTR          20
#define GSTAGE_FLOATS (2 * 128 * GSTR)       // 5120
#define GEMM_SMEM     (4 * GSTAGE_FLOATS * 4) // 81920

// Scratch (device globals — allocation-free)
__device__ float g_hid[(size_t)BATCH * S_LEN * HDIM];     // tf32-rounded hidden
__device__ float g_qkv[(size_t)BATCH * S_LEN * QKV_N];    // tf32-rounded qkv
__device__ float g_att[(size_t)BATCH * S_LEN * HDIM];     // tf32-rounded attention out
__device__ float g_wta[(size_t)QKV_N * HDIM];             // W_attn^T (rounded)
__device__ float g_wtp[(size_t)HDIM * HDIM];              // W_proj^T (rounded)

__device__ __forceinline__ uint32_t smem_u32(const void* p) {
    uint32_t a;
    asm("{ .reg .u64 t; cvta.to.shared.u64 t, %1; cvt.u32.u64 %0, t; }" : "=r"(a) : "l"(p));
    return a;
}
__device__ __forceinline__ uint32_t f2tf32(float x) {
    uint32_t r;
    asm("cvt.rna.tf32.f32 %0, %1;" : "=r"(r) : "f"(x));
    return r;
}
__device__ __forceinline__ float roundtf(float x) { return __uint_as_float(f2tf32(x)); }

__device__ __forceinline__ void cp16(uint32_t dst, const void* src) {
    asm volatile("cp.async.cg.shared.global [%0], [%1], 16;" :: "r"(dst), "l"(src));
}
#define CP_COMMIT() asm volatile("cp.async.commit_group;" ::: "memory")
#define CP_WAIT0()  asm volatile("cp.async.wait_group 0;" ::: "memory")

// m16n8k8 tf32 MMA, fp32 accumulate
__device__ __forceinline__ void mma_tf32(float* c, const uint32_t* a, const uint32_t* b) {
    asm volatile(
        "mma.sync.aligned.m16n8k8.row.col.f32.tf32.tf32.f32 "
        "{%0,%1,%2,%3}, {%4,%5,%6,%7}, {%8,%9}, {%0,%1,%2,%3};"
        : "+f"(c[0]), "+f"(c[1]), "+f"(c[2]), "+f"(c[3])
        : "r"(a[0]), "r"(a[1]), "r"(a[2]), "r"(a[3]), "r"(b[0]), "r"(b[1]));
}

// ldmatrix x4: each ret reg = one tf32 element (b16 pair) per the m8n8.b16 map.
__device__ __forceinline__ void ldsm4(uint32_t* r, uint32_t addr) {
    asm volatile("ldmatrix.sync.aligned.m8n8.x4.shared.b16 {%0,%1,%2,%3}, [%4];"
                 : "=r"(r[0]), "=r"(r[1]), "=r"(r[2]), "=r"(r[3]) : "r"(addr));
}

// ---------------------------------------------------------------------------
// Round fp32 -> tf32(rna) elementwise
// ---------------------------------------------------------------------------
__global__ void round_tf32_kernel(const float* __restrict__ in, float* __restrict__ out)
{
    const size_t i = ((size_t)blockIdx.x * blockDim.x + threadIdx.x) * 4;
    float4 v = *(const float4*)(in + i);
    v.x = roundtf(v.x); v.y = roundtf(v.y); v.z = roundtf(v.z); v.w = roundtf(v.w);
    *(float4*)(out + i) = v;
}

// ---------------------------------------------------------------------------
// Transpose + round: out[C][R] = tf32(in[R][C])
// ---------------------------------------------------------------------------
__global__ void transpose_kernel(const float* __restrict__ in, float* __restrict__ out,
                                 int R, int C)
{
    __shared__ float t[32][33];
    const int bx = blockIdx.x * 32;
    const int by = blockIdx.y * 32;
#pragma unroll
    for (int i = 0; i < 32; i += 8)
        t[threadIdx.y + i][threadIdx.x] =
            in[(size_t)(by + threadIdx.y + i) * C + bx + threadIdx.x];
    __syncthreads();
#pragma unroll
    for (int i = 0; i < 32; i += 8)
        out[(size_t)(bx + threadIdx.y + i) * R + by + threadIdx.x] =
            roundtf(t[threadIdx.x][threadIdx.y + i]);
}

// ---------------------------------------------------------------------------
// tf32 mma.sync GEMM, cp.async 4-stage, pair-chunk barriers, LDSM fragments.
// C = A @ Bt^T + bias. CTA 128x128, 256 thr, warp 64x32.
// ---------------------------------------------------------------------------
__global__ __launch_bounds__(256, 2)
void gemm_tf32_kernel(const float* __restrict__ A, const float* __restrict__ Bt,
                      const float* __restrict__ bias, float* __restrict__ C,
                      int M, int N, int K, int round_out)
{
    extern __shared__ float sm[];
    const uint32_t smb = smem_u32(sm);
    const int tid    = threadIdx.x;
    const int lane   = tid & 31;
    const int wid    = tid >> 5;
    const int g      = lane >> 2;
    const int t      = lane & 3;
    const int warp_m = wid & 1;
    const int warp_n = wid >> 1;
    const int m0     = blockIdx.y << 7;
    const int n0     = blockIdx.x << 7;

    const float* Ap = A  + (size_t)m0 * K;
    const float* Bp = Bt + (size_t)n0 * K;

    const int nchunks = K >> 4;
    const int npairs  = nchunks >> 1;
    const int fr  = tid >> 2;
    const int fc4 = (tid & 3) << 2;

    // per-lane ldmatrix row/col selectors
    const int rowin = lane & 7;
    const int rsel  = (lane >> 3) & 1;   // +8 rows (A) / k+4 (B)
    const int csel  = (lane >> 4) & 1;   // k+4 (A)  / +8 rows (B)

    // A: blocks {rows g | rows g+8} x {k | k+4}; r0..r3 = a0..a3
    const uint32_t a_lane_off =
        (uint32_t)(((warp_m * 64) + rsel * 8 + rowin) * GSTR + csel * 4) * 4;
    // B: two n-tiles per LDSM; r0..r3 = {b0,b1} of tile0, {b0,b1} of tile1
    const uint32_t b_lane_off =
        (uint32_t)(((warp_n * 32) + csel * 8 + rowin) * GSTR + rsel * 4) * 4;

    auto fill = [&](int c, int s) {
        if (c < nchunks) {
            const int kc = c << 4;
            const uint32_t sa = smb + (uint32_t)s * GSTAGE_FLOATS * 4;
#pragma unroll
            for (int i = 0; i < 2; i++) {
                const int r = fr + (i << 6);
                cp16(sa + (uint32_t)(r * GSTR + fc4) * 4,
                     Ap + (size_t)r * K + kc + fc4);
                cp16(sa + (uint32_t)((128 * GSTR) + r * GSTR + fc4) * 4,
                     Bp + (size_t)r * K + kc + fc4);
            }
        }
        CP_COMMIT();
    };

    float acc[4][4][4];
#pragma unroll
    for (int mt = 0; mt < 4; mt++)
#pragma unroll
        for (int nt = 0; nt < 4; nt++)
#pragma unroll
            for (int k = 0; k < 4; k++) acc[mt][nt][k] = 0.0f;

    float2 bv[4];
#pragma unroll
    for (int nt = 0; nt < 4; nt++)
        bv[nt] = *(const float2*)(bias + n0 + warp_n * 32 + nt * 8 + 2 * t);

    fill(0, 0); fill(1, 1);

    for (int p = 0; p < npairs; ++p) {
        const int c0 = p << 1;
        CP_WAIT0();
        __syncthreads();
        fill(c0 + 2, (c0 + 2) & 3);
        fill(c0 + 3, (c0 + 3) & 3);

#pragma unroll
        for (int half = 0; half < 2; ++half) {
            const int s = (c0 + half) & 3;
            const uint32_t sAb = smb + (uint32_t)s * GSTAGE_FLOATS * 4;
            const uint32_t sBb = sAb + 128 * GSTR * 4;
#pragma unroll
            for (int ks = 0; ks < 2; ks++) {
                const uint32_t kb = (uint32_t)(ks * 8) * 4;
                uint32_t afr[4][4], bfr[4][2];
#pragma unroll
                for (int mt = 0; mt < 4; mt++)
                    ldsm4(afr[mt], sAb + a_lane_off + kb +
                                   (uint32_t)(mt * 16 * GSTR) * 4);
#pragma unroll
                for (int nt2 = 0; nt2 < 2; nt2++) {
                    uint32_t rr[4];
                    ldsm4(rr, sBb + b_lane_off + kb +
                              (uint32_t)(nt2 * 16 * GSTR) * 4);
                    bfr[2 * nt2][0]     = rr[0];
                    bfr[2 * nt2][1]     = rr[1];
                    bfr[2 * nt2 + 1][0] = rr[2];
                    bfr[2 * nt2 + 1][1] = rr[3];
                }
#pragma unroll
                for (int mt = 0; mt < 4; mt++)
#pragma unroll
                    for (int nt = 0; nt < 4; nt++)
                        mma_tf32(acc[mt][nt], afr[mt], bfr[nt]);
            }
        }
    }

#pragma unroll
    for (int mt = 0; mt < 4; mt++) {
        const int row0 = m0 + warp_m * 64 + mt * 16 + g;
#pragma unroll
        for (int nt = 0; nt < 4; nt++) {
            const int col = n0 + warp_n * 32 + nt * 8 + 2 * t;
            float2 v0, v1;
            v0.x = acc[mt][nt][0] + bv[nt].x;
            v0.y = acc[mt][nt][1] + bv[nt].y;
            v1.x = acc[mt][nt][2] + bv[nt].x;
            v1.y = acc[mt][nt][3] + bv[nt].y;
            if (round_out) {
                v0.x = roundtf(v0.x); v0.y = roundtf(v0.y);
                v1.x = roundtf(v1.x); v1.y = roundtf(v1.y);
            }
            *(float2*)(C + (size_t)row0 * N + col)       = v0;
            *(float2*)(C + (size_t)(row0 + 8) * N + col) = v1;
        }
    }
}

// ---------------------------------------------------------------------------
// Flash attention, tf32 mma.sync + LDSM QK fragments, cp.async fills.
// q-tile 128 (8 warps x 16 rows), kv-tile 64, warp-local softmax.
// ---------------------------------------------------------------------------
__global__ __launch_bounds__(256, 1)
void attn_mma_kernel(float* __restrict__ att_out)
{
    extern __shared__ float sm[];
    const uint32_t smb = smem_u32(sm);

    const int qt  = 15 - blockIdx.x;
    const int nh  = blockIdx.y;
    const int b   = blockIdx.z;
    const int q0  = qt << 7;
    const int tid = threadIdx.x;
    const int lane = tid & 31;
    const int wid  = tid >> 5;
    const int g    = lane >> 2;
    const int t    = lane & 3;
    const int qbase = lane & 28;

    const size_t base_bh = ((size_t)b * S_LEN + (size_t)nh * HD) * QKV_N;
    const int fr  = tid >> 5;
    const int fc4 = (tid & 31) << 2;

    const int rowin = lane & 7;
    const int rsel  = (lane >> 3) & 1;
    const int csel  = (lane >> 4) & 1;
    // Q A-frag lane offset (rows wid*16 .. +15)
    const uint32_t q_lane_off =
        (uint32_t)(((wid * 16) + rsel * 8 + rowin) * AT_STR + csel * 4) * 4;
    // K B-frag lane offset (two 8-key tiles per LDSM)
    const uint32_t k_lane_off =
        (uint32_t)((csel * 8 + rowin) * AT_STR + rsel * 4) * 4;

    // ---- Q fill (cp.async) ----
#pragma unroll
    for (int i = 0; i < 16; i++) {
        const int r  = fr + (i << 3);
        const int qg = q0 + r;
        cp16(smb + (uint32_t)(r * AT_STR + fc4) * 4,
             g_qkv + base_bh + (size_t)(qg >> 4) * QKV_N + ((qg & 15) << 7) + fc4);
    }
    // ---- K/V tile 0 into stage 0 ----
    {
        const uint32_t k0b = smb + ATT_Q_FLOATS * 4;
        const uint32_t v0b = k0b + ATT_KV_FLOATS * 4;
#pragma unroll
        for (int i = 0; i < 8; i++) {
            const int r = fr + (i << 3);
            const float* p = g_qkv + base_bh + (size_t)(r >> 4) * QKV_N + ((r & 15) << 7) + fc4;
            cp16(k0b + (uint32_t)(r * AT_STR + fc4) * 4, p + HDIM);
            cp16(v0b + (uint32_t)(r * AT_STR + fc4) * 4, p + 2 * HDIM);
        }
    }
    CP_COMMIT();
    CP_WAIT0();
    __syncthreads();

    float O[16][4];
#pragma unroll
    for (int nt = 0; nt < 16; nt++)
#pragma unroll
        for (int k = 0; k < 4; k++) O[nt][k] = 0.0f;

    float m_run[2] = {-1e30f, -1e30f};
    float l_run[2] = {0.0f, 0.0f};

    const int nkt = (q0 + 128) >> 6;

    for (int kt = 0; kt < nkt; kt++) {
        const int s  = kt & 1;
        const int k0 = kt << 6;
        const uint32_t Kcb = smb + (ATT_Q_FLOATS + s * 2 * ATT_KV_FLOATS) * 4;
        const float* Vc = sm + ATT_Q_FLOATS + s * 2 * ATT_KV_FLOATS + ATT_KV_FLOATS;
        const bool pre = (kt + 1) < nkt;

        if (pre) {
            const int k0n = (kt + 1) << 6;
            const uint32_t knb = smb + (ATT_Q_FLOATS + (s ^ 1) * 2 * ATT_KV_FLOATS) * 4;
            const uint32_t vnb = knb + ATT_KV_FLOATS * 4;
#pragma unroll
            for (int i = 0; i < 8; i++) {
                const int r  = fr + (i << 3);
                const int kg = k0n + r;
                const float* p = g_qkv + base_bh + (size_t)(kg >> 4) * QKV_N +
                                 ((kg & 15) << 7) + fc4;
                cp16(knb + (uint32_t)(r * AT_STR + fc4) * 4, p + HDIM);
                cp16(vnb + (uint32_t)(r * AT_STR + fc4) * 4, p + 2 * HDIM);
            }
            CP_COMMIT();
        }

        // ---- S = Q K^T (16x64 per warp), LDSM fragments ----
        float sacc[8][4];
#pragma unroll
        for (int nt = 0; nt < 8; nt++)
#pragma unroll
            for (int k = 0; k < 4; k++) sacc[nt][k] = 0.0f;

#pragma unroll
        for (int ks = 0; ks < 16; ks++) {
            const uint32_t kb = (uint32_t)(ks * 8) * 4;
            uint32_t a[4];
            ldsm4(a, smb + q_lane_off + kb);
#pragma unroll
            for (int nt2 = 0; nt2 < 4; nt2++) {
                uint32_t rr[4];
                ldsm4(rr, Kcb + k_lane_off + kb + (uint32_t)(nt2 * 16 * AT_STR) * 4);
                uint32_t b0[2] = {rr[0], rr[1]};
                uint32_t b1[2] = {rr[2], rr[3]};
                mma_tf32(sacc[2 * nt2],     a, b0);
                mma_tf32(sacc[2 * nt2 + 1], a, b1);
            }
        }

        // ---- online softmax (warp-local; rows g and g+8) ----
        const bool crossing = (k0 + 63) > (q0 + (wid << 4));
        float pexp[2][8][2];
        float corr[2];
#pragma unroll
        for (int r = 0; r < 2; r++) {
            const int qg = q0 + (wid << 4) + g + 8 * r;
            float rm = -1e30f;
#pragma unroll
            for (int nt = 0; nt < 8; nt++) {
#pragma unroll
                for (int j = 0; j < 2; j++) {
                    float v = sacc[nt][2 * r + j] * SCALE;
                    if (crossing && (k0 + nt * 8 + 2 * t + j) > qg) v = -1e9f;
                    sacc[nt][2 * r + j] = v;
                    rm = fmaxf(rm, v);
                }
            }
            rm = fmaxf(rm, __shfl_xor_sync(0xffffffffu, rm, 1));
            rm = fmaxf(rm, __shfl_xor_sync(0xffffffffu, rm, 2));

            const float mn = fmaxf(m_run[r], rm);
            corr[r] = __expf(m_run[r] - mn);
            m_run[r] = mn;

            float rs = 0.0f;
#pragma unroll
            for (int nt = 0; nt < 8; nt++) {
#pragma unroll
                for (int j = 0; j < 2; j++) {
                    float p = __expf(sacc[nt][2 * r + j] - mn);
                    pexp[r][nt][j] = p;
                    rs += p;
                }
            }
            rs += __shfl_xor_sync(0xffffffffu, rs, 1);
            rs += __shfl_xor_sync(0xffffffffu, rs, 2);
            l_run[r] = l_run[r] * corr[r] + rs;
        }
#pragma unroll
        for (int nt = 0; nt < 16; nt++) {
            O[nt][0] *= corr[0]; O[nt][1] *= corr[0];
            O[nt][2] *= corr[1]; O[nt][3] *= corr[1];
        }

        // ---- O += P V : P A-frags via quad shuffles ----
        const int s0 = qbase + (t >> 1);
        const int s2 = s0 + 2;
        const bool odd = (t & 1);
#pragma unroll
        for (int ks = 0; ks < 8; ks++) {
            float x0 = __shfl_sync(0xffffffffu, pexp[0][ks][0], s0);
            float y0 = __shfl_sync(0xffffffffu, pexp[0][ks][1], s0);
            float x1 = __shfl_sync(0xffffffffu, pexp[1][ks][0], s0);
            float y1 = __shfl_sync(0xffffffffu, pexp[1][ks][1], s0);
            float x2 = __shfl_sync(0xffffffffu, pexp[0][ks][0], s2);
            float y2 = __shfl_sync(0xffffffffu, pexp[0][ks][1], s2);
            float x3 = __shfl_sync(0xffffffffu, pexp[1][ks][0], s2);
            float y3 = __shfl_sync(0xffffffffu, pexp[1][ks][1], s2);
            uint32_t a[4];
            a[0] = f2tf32(odd ? y0 : x0);
            a[1] = f2tf32(odd ? y1 : x1);
            a[2] = f2tf32(odd ? y2 : x2);
            a[3] = f2tf32(odd ? y3 : x3);
#pragma unroll
            for (int nt = 0; nt < 16; nt++) {
                uint32_t bfr[2];
                bfr[0] = __float_as_uint(Vc[(ks * 8 + t) * AT_STR + nt * 8 + g]);
                bfr[1] = __float_as_uint(Vc[(ks * 8 + t + 4) * AT_STR + nt * 8 + g]);
                mma_tf32(O[nt], a, bfr);
            }
        }

        CP_WAIT0();
        __syncthreads();
    }

    // ---- epilogue: normalize, round to tf32, write [b][q][nh*128 + d] ----
#pragma unroll
    for (int r = 0; r < 2; r++) {
        const float inv = 1.0f / l_run[r];
        const int qg = q0 + (wid << 4) + g + 8 * r;
        float* op = att_out + ((size_t)b * S_LEN + qg) * HDIM + nh * HD;
#pragma unroll
        for (int nt = 0; nt < 16; nt++) {
            float2 v;
            v.x = roundtf(O[nt][2 * r]     * inv);
            v.y = roundtf(O[nt][2 * r + 1] * inv);
            *(float2*)(op + nt * 8 + 2 * t) = v;
        }
    }
}

// ---------------------------------------------------------------------------
// Launch
// ---------------------------------------------------------------------------
extern "C" void kernel_launch(void* const* d_in, const int* in_sizes, int n_in,
                              void* d_out, int out_size)
{
    const float* hidden = (const float*)d_in[0];
    const float* W_attn = (const float*)d_in[2];
    const float* b_attn = (const float*)d_in[3];
    const float* W_proj = (const float*)d_in[4];
    const float* b_proj = (const float*)d_in[5];
    float* out = (float*)d_out;

    float *hid, *qkv, *att, *wta, *wtp;
    cudaGetSymbolAddress((void**)&hid, g_hid);
    cudaGetSymbolAddress((void**)&qkv, g_qkv);
    cudaGetSymbolAddress((void**)&att, g_att);
    cudaGetSymbolAddress((void**)&wta, g_wta);
    cudaGetSymbolAddress((void**)&wtp, g_wtp);

    const int M = BATCH * S_LEN;   // 4096

    // 0) Round hidden to tf32; transpose+round weights
    {
        const size_t n = (size_t)BATCH * S_LEN * HDIM;
        round_tf32_kernel<<<(int)(n / 4 / 256), 256>>>(hidden, hid);
        dim3 blk(32, 8);
        transpose_kernel<<<dim3(QKV_N / 32, HDIM / 32), blk>>>(W_attn, wta, HDIM, QKV_N);
        transpose_kernel<<<dim3(HDIM / 32, HDIM / 32), blk>>>(W_proj, wtp, HDIM, HDIM);
    }

    cudaFuncSetAttribute(gemm_tf32_kernel,
                         cudaFuncAttributeMaxDynamicSharedMemorySize, GEMM_SMEM);

    // 1) QKV projection (output rounded to tf32 for attention)
    gemm_tf32_kernel<<<dim3(QKV_N / 128, M / 128), 256, GEMM_SMEM>>>(
        hid, wta, b_attn, qkv, M, QKV_N, HDIM, 1);

    // 2) Attention (tf32 mma.sync flash; epilogue rounds for proj)
    {
        cudaFuncSetAttribute(attn_mma_kernel,
                             cudaFuncAttributeMaxDynamicSharedMemorySize, ATT_SMEM_B);
        dim3 grid(S_LEN / 128, NHEADS, BATCH);
        attn_mma_kernel<<<grid, 256, ATT_SMEM_B>>>(att);
    }

    // 3) Output projection (full fp32 output)
    gemm_tf32_kernel<<<dim3(HDIM / 128, M / 128), 256, GEMM_SMEM>>>(
        att, wtp, b_proj, out, M, HDIM, HDIM, 0);
}